// round 1
// baseline (speedup 1.0000x reference)
#include <cuda_runtime.h>
#include <math.h>

#define NP 2048
#define EP 512
#define HH 8
#define DD 64
#define BB 2
#define MT (BB*NP)   // 4096 rows total

// ---------------- scratch (device globals; no allocation) ----------------
__device__ __align__(16) float g_sin[NP*32];
__device__ __align__(16) float g_cos[NP*32];
__device__ __align__(16) float g_scale[NP*32];
__device__ __align__(16) float g_Q[MT*EP];
__device__ __align__(16) float g_K[MT*EP];
__device__ __align__(16) float g_V[MT*EP];
__device__ __align__(16) float g_G[MT*EP];
__device__ __align__(16) float g_RG[MT*EP];

// ---------------- xpos tables ----------------
__global__ void build_tables() {
    int idx = blockIdx.x * 256 + threadIdx.x;   // NP*32 = 65536
    if (idx >= NP*32) return;
    int n = idx >> 5;
    int j = idx & 31;
    // inv_freq = 10000^{-j/32}
    float inv_freq = expf(-(float)j * (9.210340371976184f / 32.f));
    float s, c;
    sincosf((float)n * inv_freq, &s, &c);
    // xscale = (2j + 0.4*64)/(1.4*64); scale = xscale^((n - N/2)/512)
    float xscale = (2.f*(float)j + 25.6f) / 89.6f;
    float power = ((float)n - 1024.f) * (1.f/512.f);
    float sc = expf(power * logf(xscale));
    g_sin[idx] = s; g_cos[idx] = c; g_scale[idx] = sc;
}

// ---------------- GEMM: C[M,512] = A[M,512] @ W^T + bias, fused epilogue ----------------
// EPI: 0=none, 1=silu, 2=xpos(q), 3=xpos(k) * 1/sqrt(D)
template<int EPI>
__global__ void __launch_bounds__(256) gemm_bias_kernel(
    const float* __restrict__ A, const float* __restrict__ W,
    const float* __restrict__ bias, float* __restrict__ C)
{
    __shared__ float As[16*132];
    __shared__ float Bs[16*132];
    int tid = threadIdx.x;
    int tx = tid & 15, ty = tid >> 4;
    int n0 = blockIdx.x * 128;
    int m0 = blockIdx.y * 128;

    float acc[8][8] = {};

    for (int kt = 0; kt < EP; kt += 16) {
        #pragma unroll
        for (int r = 0; r < 2; r++) {
            int f  = tid + r*256;
            int mm = f >> 2;
            int k4 = (f & 3) * 4;
            float4 a4 = *(const float4*)(A + (size_t)(m0+mm)*EP + kt + k4);
            As[(k4+0)*132+mm]=a4.x; As[(k4+1)*132+mm]=a4.y;
            As[(k4+2)*132+mm]=a4.z; As[(k4+3)*132+mm]=a4.w;
            float4 b4 = *(const float4*)(W + (size_t)(n0+mm)*EP + kt + k4);
            Bs[(k4+0)*132+mm]=b4.x; Bs[(k4+1)*132+mm]=b4.y;
            Bs[(k4+2)*132+mm]=b4.z; Bs[(k4+3)*132+mm]=b4.w;
        }
        __syncthreads();
        #pragma unroll
        for (int kk = 0; kk < 16; kk++) {
            float ra[8], rb[8];
            *(float4*)(ra)   = *(const float4*)(As + kk*132 + ty*8);
            *(float4*)(ra+4) = *(const float4*)(As + kk*132 + ty*8 + 4);
            *(float4*)(rb)   = *(const float4*)(Bs + kk*132 + tx*8);
            *(float4*)(rb+4) = *(const float4*)(Bs + kk*132 + tx*8 + 4);
            #pragma unroll
            for (int i = 0; i < 8; i++)
                #pragma unroll
                for (int j = 0; j < 8; j++)
                    acc[i][j] += ra[i] * rb[j];
        }
        __syncthreads();
    }

    float bb[8];
    #pragma unroll
    for (int j = 0; j < 8; j++) bb[j] = bias[n0 + tx*8 + j];

    #pragma unroll
    for (int i = 0; i < 8; i++) {
        int m = m0 + ty*8 + i;
        float o[8];
        #pragma unroll
        for (int j = 0; j < 8; j++) o[j] = acc[i][j] + bb[j];

        if (EPI == 1) {
            #pragma unroll
            for (int j = 0; j < 8; j++) o[j] = o[j] / (1.f + expf(-o[j]));
        } else if (EPI == 2 || EPI == 3) {
            int npos = m & (NP - 1);
            #pragma unroll
            for (int p = 0; p < 4; p++) {
                int col = n0 + tx*8 + 2*p;
                int j2  = (col & 63) >> 1;
                float sn = g_sin[npos*32 + j2];
                float cs = g_cos[npos*32 + j2];
                float sc = g_scale[npos*32 + j2];
                if (EPI == 3) sc = 1.f / sc;
                float s = sn * sc, c = cs * sc;
                float x0 = o[2*p], x1 = o[2*p+1];
                float y0 = x0*c - x1*s;
                float y1 = x1*c + x0*s;
                if (EPI == 3) { y0 *= 0.125f; y1 *= 0.125f; }
                o[2*p] = y0; o[2*p+1] = y1;
            }
        }
        *(float4*)(C + (size_t)m*EP + n0 + tx*8)     = *(float4*)(o);
        *(float4*)(C + (size_t)m*EP + n0 + tx*8 + 4) = *(float4*)(o + 4);
    }
}

// ---------------- retention: sim=q.k^T * decay, ret=sim@v, groupnorm, *gate ----------------
// grid: (N/64, H, B). smem: Qs[64][65] | Ks[64][65] (reused as Sim[s][n]) | Vs[64][64]
__global__ void __launch_bounds__(256) retention_kernel(
    const float* __restrict__ Q, const float* __restrict__ K,
    const float* __restrict__ V, const float* __restrict__ G,
    float* __restrict__ RG)
{
    extern __shared__ float sm[];
    float* Qs = sm;            // 64*65
    float* Ks = sm + 4160;     // 64*65 (doubles as Sim[s][n])
    float* Vs = sm + 8320;     // 64*64

    int qt = blockIdx.x, h = blockIdx.y, b = blockIdx.z;
    int tid = threadIdx.x;
    int tx = tid & 15, ty = tid >> 4;

    // gammas = 1 - exp(linspace(ln(1/32), ln(1/512), 8))
    float gamma = 1.f - expf(-(3.465735902799726f + 0.396084103177426f * (float)h));
    float l2g = log2f(gamma);

    // load Q tile transposed: Qs[d][n]
    const float* qg = Q + ((size_t)(b*NP + qt*64))*EP + h*64;
    #pragma unroll
    for (int r = 0; r < 4; r++) {
        int n  = (tid >> 4) + r*16;
        int d4 = (tid & 15) * 4;
        float4 v4 = *(const float4*)(qg + (size_t)n*EP + d4);
        Qs[(d4+0)*65+n]=v4.x; Qs[(d4+1)*65+n]=v4.y;
        Qs[(d4+2)*65+n]=v4.z; Qs[(d4+3)*65+n]=v4.w;
    }

    float acc[4][4] = {};

    for (int st = 0; st <= qt; st++) {
        __syncthreads();   // protect Ks/Vs from previous iteration's readers
        const float* kg = K + ((size_t)(b*NP + st*64))*EP + h*64;
        const float* vg = V + ((size_t)(b*NP + st*64))*EP + h*64;
        #pragma unroll
        for (int r = 0; r < 4; r++) {
            int s  = (tid >> 4) + r*16;
            int d4 = (tid & 15) * 4;
            float4 v4 = *(const float4*)(kg + (size_t)s*EP + d4);
            Ks[(d4+0)*65+s]=v4.x; Ks[(d4+1)*65+s]=v4.y;
            Ks[(d4+2)*65+s]=v4.z; Ks[(d4+3)*65+s]=v4.w;
            int f  = tid + r*256;
            int sv = f >> 4;
            int dv4 = (f & 15) * 4;
            *(float4*)(Vs + sv*64 + dv4) = *(const float4*)(vg + (size_t)sv*EP + dv4);
        }
        __syncthreads();

        // sim[n][s] = sum_d Qs[d][n] * Ks[d][s]
        float sim[4][4] = {};
        #pragma unroll
        for (int d = 0; d < 64; d++) {
            float qv[4], kv[4];
            #pragma unroll
            for (int i = 0; i < 4; i++) qv[i] = Qs[d*65 + ty*4 + i];
            #pragma unroll
            for (int j = 0; j < 4; j++) kv[j] = Ks[d*65 + tx*4 + j];
            #pragma unroll
            for (int i = 0; i < 4; i++)
                #pragma unroll
                for (int j = 0; j < 4; j++)
                    sim[i][j] += qv[i] * kv[j];
        }
        // decay + causal mask
        #pragma unroll
        for (int i = 0; i < 4; i++) {
            int n = qt*64 + ty*4 + i;
            #pragma unroll
            for (int j = 0; j < 4; j++) {
                int s = st*64 + tx*4 + j;
                int dist = n - s;
                sim[i][j] = (dist >= 0) ? sim[i][j] * exp2f((float)dist * l2g) : 0.f;
            }
        }
        __syncthreads();
        // store Sim[s][n] into Ks buffer
        #pragma unroll
        for (int i = 0; i < 4; i++)
            #pragma unroll
            for (int j = 0; j < 4; j++)
                Ks[(tx*4+j)*65 + ty*4 + i] = sim[i][j];
        __syncthreads();
        // acc[n][d] += sum_s Sim[s][n] * Vs[s][d]
        #pragma unroll
        for (int s = 0; s < 64; s++) {
            float sv[4], vv[4];
            #pragma unroll
            for (int i = 0; i < 4; i++) sv[i] = Ks[s*65 + ty*4 + i];
            #pragma unroll
            for (int j = 0; j < 4; j++) vv[j] = Vs[s*64 + tx*4 + j];
            #pragma unroll
            for (int i = 0; i < 4; i++)
                #pragma unroll
                for (int j = 0; j < 4; j++)
                    acc[i][j] += sv[i] * vv[j];
        }
    }

    // groupnorm over D=64 (per row) + gate multiply + write
    #pragma unroll
    for (int i = 0; i < 4; i++) {
        float s1 = 0.f, s2 = 0.f;
        #pragma unroll
        for (int j = 0; j < 4; j++) { s1 += acc[i][j]; s2 += acc[i][j]*acc[i][j]; }
        #pragma unroll
        for (int off = 8; off >= 1; off >>= 1) {
            s1 += __shfl_xor_sync(0xffffffffu, s1, off);
            s2 += __shfl_xor_sync(0xffffffffu, s2, off);
        }
        float mean = s1 * (1.f/64.f);
        float var  = s2 * (1.f/64.f) - mean*mean;
        float inv  = rsqrtf(var + 1e-6f);
        int n = qt*64 + ty*4 + i;
        size_t base = ((size_t)(b*NP + n))*EP + h*64 + tx*4;
        float4 g4 = *(const float4*)(G + base);
        float4 o;
        o.x = (acc[i][0]-mean)*inv * g4.x;
        o.y = (acc[i][1]-mean)*inv * g4.y;
        o.z = (acc[i][2]-mean)*inv * g4.z;
        o.w = (acc[i][3]-mean)*inv * g4.w;
        *(float4*)(RG + base) = o;
    }
}

// ---------------- launch ----------------
extern "C" void kernel_launch(void* const* d_in, const int* in_sizes, int n_in,
                              void* d_out, int out_size) {
    const float* query = (const float*)d_in[0];
    const float* key   = (const float*)d_in[1];
    const float* value = (const float*)d_in[2];
    const float* Wq = (const float*)d_in[3];
    const float* bq = (const float*)d_in[4];
    const float* Wk = (const float*)d_in[5];
    const float* bk = (const float*)d_in[6];
    const float* Wv = (const float*)d_in[7];
    const float* bv = (const float*)d_in[8];
    const float* Wg = (const float*)d_in[9];
    const float* bg = (const float*)d_in[10];
    const float* Wo = (const float*)d_in[11];
    const float* bo = (const float*)d_in[12];
    float* out = (float*)d_out;

    float *Qb, *Kb, *Vb, *Gb, *RGb;
    cudaGetSymbolAddress((void**)&Qb,  g_Q);
    cudaGetSymbolAddress((void**)&Kb,  g_K);
    cudaGetSymbolAddress((void**)&Vb,  g_V);
    cudaGetSymbolAddress((void**)&Gb,  g_G);
    cudaGetSymbolAddress((void**)&RGb, g_RG);

    build_tables<<<(NP*32)/256, 256>>>();

    dim3 gg(EP/128, MT/128);   // (4, 32)
    gemm_bias_kernel<2><<<gg, 256>>>(query, Wq, bq, Qb);   // Q proj + xpos
    gemm_bias_kernel<3><<<gg, 256>>>(key,   Wk, bk, Kb);   // K proj + xpos^-1 + 1/sqrt(D)
    gemm_bias_kernel<0><<<gg, 256>>>(value, Wv, bv, Vb);   // V proj
    gemm_bias_kernel<1><<<gg, 256>>>(query, Wg, bg, Gb);   // gate proj + silu

    size_t smem_ret = (4160 + 4160 + 4096) * sizeof(float);   // 49664 B
    cudaFuncSetAttribute(retention_kernel,
                         cudaFuncAttributeMaxDynamicSharedMemorySize, (int)smem_ret);
    retention_kernel<<<dim3(NP/64, HH, BB), 256, smem_ret>>>(Qb, Kb, Vb, Gb, RGb);

    gemm_bias_kernel<0><<<gg, 256>>>(RGb, Wo, bo, out);    // output proj
}

// round 4
// speedup vs baseline: 2.2314x; 2.2314x over previous
#include <cuda_runtime.h>
#include <cuda_bf16.h>
#include <math.h>
#include <stdint.h>

#define NP 2048
#define EP 512
#define MT 4096

// ---------------- device scratch ----------------
__device__ __align__(16) float g_sin[NP*32];
__device__ __align__(16) float g_cos[NP*32];
__device__ __align__(16) float g_scale[NP*32];
__device__ __align__(16) __nv_bfloat16 g_INh[3][MT*EP];
__device__ __align__(16) __nv_bfloat16 g_INl[3][MT*EP];
__device__ __align__(16) __nv_bfloat16 g_Wh[5][EP*EP];
__device__ __align__(16) __nv_bfloat16 g_Wl[5][EP*EP];
__device__ __align__(16) __nv_bfloat16 g_Qh[MT*EP], g_Ql[MT*EP];
__device__ __align__(16) __nv_bfloat16 g_Kh[MT*EP], g_Kl[MT*EP];
__device__ __align__(16) __nv_bfloat16 g_Vh[MT*EP], g_Vl[MT*EP];
__device__ __align__(16) __nv_bfloat16 g_RGh[MT*EP], g_RGl[MT*EP];
__device__ __align__(16) float g_G[MT*EP];

// ---------------- helpers ----------------
__device__ __forceinline__ uint32_t smem_u32(const void* p) {
    uint32_t a;
    asm("{ .reg .u64 t; cvta.to.shared.u64 t, %1; cvt.u32.u64 %0, t; }" : "=r"(a) : "l"(p));
    return a;
}
__device__ __forceinline__ void ldsm4(uint32_t* r, uint32_t a) {
    asm volatile("ldmatrix.sync.aligned.m8n8.x4.shared.b16 {%0,%1,%2,%3}, [%4];"
        : "=r"(r[0]), "=r"(r[1]), "=r"(r[2]), "=r"(r[3]) : "r"(a));
}
__device__ __forceinline__ void ldsm4t(uint32_t* r, uint32_t a) {
    asm volatile("ldmatrix.sync.aligned.m8n8.x4.trans.shared.b16 {%0,%1,%2,%3}, [%4];"
        : "=r"(r[0]), "=r"(r[1]), "=r"(r[2]), "=r"(r[3]) : "r"(a));
}
__device__ __forceinline__ void mma_bf16(float* c, const uint32_t* a, uint32_t b0, uint32_t b1) {
    asm volatile("mma.sync.aligned.m16n8k16.row.col.f32.bf16.bf16.f32 "
        "{%0,%1,%2,%3}, {%4,%5,%6,%7}, {%8,%9}, {%0,%1,%2,%3};"
        : "+f"(c[0]), "+f"(c[1]), "+f"(c[2]), "+f"(c[3])
        : "r"(a[0]), "r"(a[1]), "r"(a[2]), "r"(a[3]), "r"(b0), "r"(b1));
}
__device__ __forceinline__ void split_pair(float v0, float v1, uint32_t& hi, uint32_t& lo) {
    __nv_bfloat16 h0 = __float2bfloat16_rn(v0);
    __nv_bfloat16 h1 = __float2bfloat16_rn(v1);
    __nv_bfloat16 l0 = __float2bfloat16_rn(v0 - __bfloat162float(h0));
    __nv_bfloat16 l1 = __float2bfloat16_rn(v1 - __bfloat162float(h1));
    __nv_bfloat162 H = __halves2bfloat162(h0, h1);
    __nv_bfloat162 L = __halves2bfloat162(l0, l1);
    hi = *reinterpret_cast<uint32_t*>(&H);
    lo = *reinterpret_cast<uint32_t*>(&L);
}

// ---------------- xpos tables ----------------
__global__ void build_tables() {
    int idx = blockIdx.x * 256 + threadIdx.x;
    if (idx >= NP*32) return;
    int n = idx >> 5, j = idx & 31;
    float inv_freq = expf(-(float)j * (9.210340371976184f / 32.f));
    float s, c;
    sincosf((float)n * inv_freq, &s, &c);
    float xscale = (2.f*(float)j + 25.6f) / 89.6f;
    float power = ((float)n - 1024.f) * (1.f/512.f);
    g_sin[idx] = s; g_cos[idx] = c; g_scale[idx] = expf(power * logf(xscale));
}

// ---------------- hi/lo pre-split ----------------
__global__ void convert_in(const float* __restrict__ q, const float* __restrict__ k,
                           const float* __restrict__ v) {
    int z = blockIdx.y;
    const float* src = (z == 0) ? q : (z == 1) ? k : v;
    int idx = (blockIdx.x * 256 + threadIdx.x) * 4;
    float4 x = *(const float4*)(src + idx);
    uint32_t h0,l0,h1,l1;
    split_pair(x.x, x.y, h0, l0);
    split_pair(x.z, x.w, h1, l1);
    *(uint2*)(&g_INh[z][idx]) = make_uint2(h0, h1);
    *(uint2*)(&g_INl[z][idx]) = make_uint2(l0, l1);
}
__global__ void convert_w(const float* __restrict__ w0, const float* __restrict__ w1,
                          const float* __restrict__ w2, const float* __restrict__ w3,
                          const float* __restrict__ w4) {
    int z = blockIdx.y;
    const float* src = (z == 0) ? w0 : (z == 1) ? w1 : (z == 2) ? w2 : (z == 3) ? w3 : w4;
    int idx = (blockIdx.x * 256 + threadIdx.x) * 4;
    float4 x = *(const float4*)(src + idx);
    uint32_t h0,l0,h1,l1;
    split_pair(x.x, x.y, h0, l0);
    split_pair(x.z, x.w, h1, l1);
    *(uint2*)(&g_Wh[z][idx]) = make_uint2(h0, h1);
    *(uint2*)(&g_Wl[z][idx]) = make_uint2(l0, l1);
}

// ================= projection GEMM (bf16x3 mma.sync) =================
// buf layout (per 40960B buffer): AH@0 AL@10240 BH@20480 BL@30720; row stride 80B.
#define PROJ_SMEM 81920

__device__ __forceinline__ void proj_body(
    const __nv_bfloat16* __restrict__ Ah, const __nv_bfloat16* __restrict__ Al,
    const __nv_bfloat16* __restrict__ Bh, const __nv_bfloat16* __restrict__ Bl,
    const float* __restrict__ bias, int epi,
    float* Cf, __nv_bfloat16* Ch, __nv_bfloat16* Cl, char* sm)
{
    const int tid = threadIdx.x, lane = tid & 31, wid = tid >> 5;
    const int wm = wid & 3, wn = wid >> 2;
    const int n0 = blockIdx.x * 128, m0 = blockIdx.y * 128;
    const uint32_t sb = smem_u32(sm);
    float acc[2][8][4] = {};
    uint4 pa[2][2], pb[2][2];

    #pragma unroll
    for (int i = 0; i < 2; i++) {
        int t = tid + i*256; int row = t >> 2, seg = t & 3;
        size_t ga = (size_t)(m0 + row)*EP + seg*8;
        size_t gb = (size_t)(n0 + row)*EP + seg*8;
        pa[0][i] = *(const uint4*)(Ah + ga); pa[1][i] = *(const uint4*)(Al + ga);
        pb[0][i] = *(const uint4*)(Bh + gb); pb[1][i] = *(const uint4*)(Bl + gb);
    }
    for (int kc = 0; kc < 16; kc++) {
        char* bp = sm + (kc & 1) * 40960;
        #pragma unroll
        for (int i = 0; i < 2; i++) {
            int t = tid + i*256; int row = t >> 2, seg = t & 3;
            *(uint4*)(bp +         row*80 + seg*16) = pa[0][i];
            *(uint4*)(bp + 10240 + row*80 + seg*16) = pa[1][i];
            *(uint4*)(bp + 20480 + row*80 + seg*16) = pb[0][i];
            *(uint4*)(bp + 30720 + row*80 + seg*16) = pb[1][i];
        }
        __syncthreads();
        if (kc < 15) {
            #pragma unroll
            for (int i = 0; i < 2; i++) {
                int t = tid + i*256; int row = t >> 2, seg = t & 3;
                size_t ga = (size_t)(m0 + row)*EP + (kc+1)*32 + seg*8;
                size_t gb = (size_t)(n0 + row)*EP + (kc+1)*32 + seg*8;
                pa[0][i] = *(const uint4*)(Ah + ga); pa[1][i] = *(const uint4*)(Al + ga);
                pb[0][i] = *(const uint4*)(Bh + gb); pb[1][i] = *(const uint4*)(Bl + gb);
            }
        }
        const uint32_t base = sb + (kc & 1) * 40960;
        #pragma unroll
        for (int kk = 0; kk < 2; kk++) {
            uint32_t ah[2][4], al[2][4];
            #pragma unroll
            for (int mt = 0; mt < 2; mt++) {
                uint32_t off = (uint32_t)(wm*32 + mt*16 + (lane & 15))*80 + kk*32 + ((lane >> 4) & 1)*16;
                ldsm4(ah[mt], base + off);
                ldsm4(al[mt], base + 10240 + off);
            }
            uint32_t bh[4][4], bl[4][4];
            #pragma unroll
            for (int jt = 0; jt < 4; jt++) {
                uint32_t off = (uint32_t)(wn*64 + jt*16 + (lane & 7) + ((lane & 16) ? 8 : 0))*80
                             + kk*32 + ((lane & 8) ? 16 : 0);
                ldsm4(bh[jt], base + 20480 + off);
                ldsm4(bl[jt], base + 30720 + off);
            }
            #pragma unroll
            for (int mt = 0; mt < 2; mt++)
                #pragma unroll
                for (int nt = 0; nt < 8; nt++) {
                    int jt = nt >> 1, o = (nt & 1)*2;
                    mma_bf16(acc[mt][nt], ah[mt], bh[jt][o], bh[jt][o+1]);
                    mma_bf16(acc[mt][nt], ah[mt], bl[jt][o], bl[jt][o+1]);
                    mma_bf16(acc[mt][nt], al[mt], bh[jt][o], bh[jt][o+1]);
                }
        }
        __syncthreads();
    }

    #pragma unroll
    for (int mt = 0; mt < 2; mt++) {
        #pragma unroll
        for (int rr = 0; rr < 2; rr++) {
            int row = m0 + wm*32 + mt*16 + (lane >> 2) + rr*8;
            int npos = row & (NP - 1);
            #pragma unroll
            for (int nt = 0; nt < 8; nt++) {
                int col = n0 + wn*64 + nt*8 + 2*(lane & 3);
                float x0 = acc[mt][nt][rr*2]     + bias[col];
                float x1 = acc[mt][nt][rr*2 + 1] + bias[col + 1];
                if (epi == 1) {
                    x0 = x0 / (1.f + expf(-x0));
                    x1 = x1 / (1.f + expf(-x1));
                } else if (epi == 2 || epi == 3) {
                    int j2 = (col & 63) >> 1;
                    float sn = g_sin[npos*32 + j2];
                    float cs = g_cos[npos*32 + j2];
                    float sc = g_scale[npos*32 + j2];
                    if (epi == 3) sc = 1.f / sc;
                    float s = sn * sc, c = cs * sc;
                    float y0 = x0 * c - x1 * s;
                    float y1 = x1 * c + x0 * s;
                    if (epi == 3) { y0 *= 0.125f; y1 *= 0.125f; }
                    x0 = y0; x1 = y1;
                }
                size_t off = (size_t)row*EP + col;
                if (Ch) {
                    uint32_t hh, ll;
                    split_pair(x0, x1, hh, ll);
                    *(uint32_t*)(Ch + off) = hh;
                    *(uint32_t*)(Cl + off) = ll;
                } else {
                    *(float2*)(Cf + off) = make_float2(x0, x1);
                }
            }
        }
    }
}

__global__ void __launch_bounds__(256) qkvg_kernel(
    const float* __restrict__ bq, const float* __restrict__ bk,
    const float* __restrict__ bv, const float* __restrict__ bg)
{
    extern __shared__ char sm[];
    const int z = blockIdx.z;
    const __nv_bfloat16* Ah = g_INh[(z == 3) ? 0 : z];
    const __nv_bfloat16* Al = g_INl[(z == 3) ? 0 : z];
    const float* bias = (z == 0) ? bq : (z == 1) ? bk : (z == 2) ? bv : bg;
    __nv_bfloat16* Ch = (z == 0) ? g_Qh : (z == 1) ? g_Kh : (z == 2) ? g_Vh : (__nv_bfloat16*)0;
    __nv_bfloat16* Cl = (z == 0) ? g_Ql : (z == 1) ? g_Kl : (z == 2) ? g_Vl : (__nv_bfloat16*)0;
    float* Cf = (z == 3) ? g_G : (float*)0;
    const int epi = (z == 0) ? 2 : (z == 1) ? 3 : (z == 2) ? 0 : 1;
    proj_body(Ah, Al, g_Wh[z], g_Wl[z], bias, epi, Cf, Ch, Cl, sm);
}

__global__ void __launch_bounds__(256) out_kernel(const float* __restrict__ bo,
                                                  float* __restrict__ out)
{
    extern __shared__ char sm[];
    proj_body(g_RGh, g_RGl, g_Wh[4], g_Wl[4], bo, 0, out, (__nv_bfloat16*)0, (__nv_bfloat16*)0, sm);
}

// ================= retention (bf16x3 mma.sync) =================
// smem: QH 0 (128x144B) QL 18432 | KH 36864 (64x144) KL 46080 | VH 55296 VL 64512
//       SH 73728 (128x144, warp-private 16-row slices) SL 92160 ; total 110592
#define RSM_QH 0u
#define RSM_QL 18432u
#define RSM_KH 36864u
#define RSM_KL 46080u
#define RSM_VH 55296u
#define RSM_VL 64512u
#define RSM_SH 73728u
#define RSM_SL 92160u
#define RET_SMEM 110592u

__global__ void __launch_bounds__(256, 1) retention_kernel()
{
    extern __shared__ char sm[];
    const int tid = threadIdx.x, lane = tid & 31, wid = tid >> 5;
    const int qt = 15 - (int)blockIdx.x;     // heaviest tiles first
    const int h = blockIdx.y, b = blockIdx.z;
    const uint32_t sb = smem_u32(sm);

    const float gamma = 1.f - expf(-(3.465735902799726f + 0.396084103177426f * (float)h));
    const float l2g = log2f(gamma);

    // load Q tile 128x64 (hi/lo)
    #pragma unroll
    for (int i = 0; i < 4; i++) {
        int t = tid + i*256; int row = t >> 3, seg = t & 7;
        size_t ga = (size_t)(b*NP + qt*128 + row)*EP + h*64 + seg*8;
        *(uint4*)(sm + RSM_QH + row*144 + seg*16) = *(const uint4*)(g_Qh + ga);
        *(uint4*)(sm + RSM_QL + row*144 + seg*16) = *(const uint4*)(g_Ql + ga);
    }
    __syncthreads();

    // cache Q fragments in registers
    uint32_t qh[4][4], ql[4][4];
    #pragma unroll
    for (int kk = 0; kk < 4; kk++) {
        uint32_t off = (uint32_t)(wid*16 + (lane & 15))*144 + kk*32 + ((lane >> 4) & 1)*16;
        ldsm4(qh[kk], sb + RSM_QH + off);
        ldsm4(ql[kk], sb + RSM_QL + off);
    }

    float colf[16];
    #pragma unroll
    for (int nt = 0; nt < 8; nt++) {
        int sl = nt*8 + 2*(lane & 3);
        colf[nt*2]   = exp2f(-l2g * (float)sl);
        colf[nt*2+1] = exp2f(-l2g * (float)(sl + 1));
    }
    const int nl0 = wid*16 + (lane >> 2);
    float ret[8][4] = {};
    const int n_st = 2*qt + 2;

    uint4 pk[2][2], pv[2][2];
    #pragma unroll
    for (int i = 0; i < 2; i++) {
        int t = tid + i*256; int row = t >> 3, seg = t & 7;
        size_t ga = (size_t)(b*NP + row)*EP + h*64 + seg*8;
        pk[0][i] = *(const uint4*)(g_Kh + ga); pk[1][i] = *(const uint4*)(g_Kl + ga);
        pv[0][i] = *(const uint4*)(g_Vh + ga); pv[1][i] = *(const uint4*)(g_Vl + ga);
    }
    const uint32_t swh = sb + RSM_SH + wid*2304;
    const uint32_t swl = sb + RSM_SL + wid*2304;

    for (int st = 0; st < n_st; st++) {
        __syncthreads();
        #pragma unroll
        for (int i = 0; i < 2; i++) {
            int t = tid + i*256; int row = t >> 3, seg = t & 7;
            *(uint4*)(sm + RSM_KH + row*144 + seg*16) = pk[0][i];
            *(uint4*)(sm + RSM_KL + row*144 + seg*16) = pk[1][i];
            *(uint4*)(sm + RSM_VH + row*144 + seg*16) = pv[0][i];
            *(uint4*)(sm + RSM_VL + row*144 + seg*16) = pv[1][i];
        }
        __syncthreads();
        if (st + 1 < n_st) {
            #pragma unroll
            for (int i = 0; i < 2; i++) {
                int t = tid + i*256; int row = t >> 3, seg = t & 7;
                size_t ga = (size_t)(b*NP + (st+1)*64 + row)*EP + h*64 + seg*8;
                pk[0][i] = *(const uint4*)(g_Kh + ga); pk[1][i] = *(const uint4*)(g_Kl + ga);
                pv[0][i] = *(const uint4*)(g_Vh + ga); pv[1][i] = *(const uint4*)(g_Vl + ga);
            }
        }

        // gemm1: sim = Q K^T  (k = d = 64)
        float simf[8][4] = {};
        #pragma unroll
        for (int kk = 0; kk < 4; kk++) {
            uint32_t bh[4][4], bl[4][4];
            #pragma unroll
            for (int jt = 0; jt < 4; jt++) {
                uint32_t off = (uint32_t)(jt*16 + (lane & 7) + ((lane & 16) ? 8 : 0))*144
                             + kk*32 + ((lane & 8) ? 16 : 0);
                ldsm4(bh[jt], sb + RSM_KH + off);
                ldsm4(bl[jt], sb + RSM_KL + off);
            }
            #pragma unroll
            for (int nt = 0; nt < 8; nt++) {
                int jt = nt >> 1, o = (nt & 1)*2;
                mma_bf16(simf[nt], qh[kk], bh[jt][o], bh[jt][o+1]);
                mma_bf16(simf[nt], qh[kk], bl[jt][o], bl[jt][o+1]);
                mma_bf16(simf[nt], ql[kk], bh[jt][o], bh[jt][o+1]);
            }
        }

        // decay + mask + split -> warp sim smem
        const int db = qt*128 - st*64;
        const float brf0 = exp2f(l2g * (float)(db + nl0));
        const float brf1 = exp2f(l2g * (float)(db + nl0 + 8));
        #pragma unroll
        for (int nt = 0; nt < 8; nt++) {
            int sl0 = nt*8 + 2*(lane & 3);
            float v00 = (db + nl0 - sl0     >= 0) ? simf[nt][0]*brf0*colf[nt*2]   : 0.f;
            float v01 = (db + nl0 - sl0 - 1 >= 0) ? simf[nt][1]*brf0*colf[nt*2+1] : 0.f;
            float v10 = (db + nl0 + 8 - sl0     >= 0) ? simf[nt][2]*brf1*colf[nt*2]   : 0.f;
            float v11 = (db + nl0 + 8 - sl0 - 1 >= 0) ? simf[nt][3]*brf1*colf[nt*2+1] : 0.f;
            uint32_t hh, ll;
            uint32_t so0 = (uint32_t)(lane >> 2)*144 + sl0*2;
            split_pair(v00, v01, hh, ll);
            *(uint32_t*)(sm + RSM_SH + wid*2304 + so0) = hh;
            *(uint32_t*)(sm + RSM_SL + wid*2304 + so0) = ll;
            split_pair(v10, v11, hh, ll);
            *(uint32_t*)(sm + RSM_SH + wid*2304 + so0 + 8*144) = hh;
            *(uint32_t*)(sm + RSM_SL + wid*2304 + so0 + 8*144) = ll;
        }
        __syncwarp();

        // gemm2: ret += sim @ V
        #pragma unroll
        for (int kk = 0; kk < 4; kk++) {
            uint32_t ah2[4], al2[4];
            uint32_t aoff = (uint32_t)(lane & 15)*144 + kk*32 + ((lane >> 4) & 1)*16;
            ldsm4(ah2, swh + aoff);
            ldsm4(al2, swl + aoff);
            uint32_t bh[4][4], bl[4][4];
            #pragma unroll
            for (int dt = 0; dt < 4; dt++) {
                uint32_t off = (uint32_t)(kk*16 + (lane & 15))*144 + dt*32 + ((lane >> 4) & 1)*16;
                ldsm4t(bh[dt], sb + RSM_VH + off);
                ldsm4t(bl[dt], sb + RSM_VL + off);
            }
            #pragma unroll
            for (int nt = 0; nt < 8; nt++) {
                int dt = nt >> 1, o = (nt & 1)*2;
                mma_bf16(ret[nt], ah2, bh[dt][o], bh[dt][o+1]);
                mma_bf16(ret[nt], ah2, bl[dt][o], bl[dt][o+1]);
                mma_bf16(ret[nt], al2, bh[dt][o], bh[dt][o+1]);
            }
        }
        __syncwarp();
    }

    // groupnorm over d=64 per row + gate + write hi/lo planes
    #pragma unroll
    for (int rr = 0; rr < 2; rr++) {
        float s1 = 0.f, s2 = 0.f;
        #pragma unroll
        for (int nt = 0; nt < 8; nt++) {
            float a = ret[nt][rr*2], c = ret[nt][rr*2+1];
            s1 += a + c; s2 += a*a + c*c;
        }
        s1 += __shfl_xor_sync(0xffffffffu, s1, 1); s2 += __shfl_xor_sync(0xffffffffu, s2, 1);
        s1 += __shfl_xor_sync(0xffffffffu, s1, 2); s2 += __shfl_xor_sync(0xffffffffu, s2, 2);
        float mean = s1 * (1.f/64.f);
        float var  = s2 * (1.f/64.f) - mean*mean;
        float inv  = rsqrtf(var + 1e-6f);
        int row = qt*128 + nl0 + rr*8;
        size_t base = (size_t)(b*NP + row)*EP + h*64;
        #pragma unroll
        for (int nt = 0; nt < 8; nt++) {
            int col = nt*8 + 2*(lane & 3);
            float2 g2 = *(const float2*)(g_G + base + col);
            float x0 = (ret[nt][rr*2]   - mean)*inv * g2.x;
            float x1 = (ret[nt][rr*2+1] - mean)*inv * g2.y;
            uint32_t hh, ll;
            split_pair(x0, x1, hh, ll);
            *(uint32_t*)(g_RGh + base + col) = hh;
            *(uint32_t*)(g_RGl + base + col) = ll;
        }
    }
}

// ---------------- launch ----------------
extern "C" void kernel_launch(void* const* d_in, const int* in_sizes, int n_in,
                              void* d_out, int out_size) {
    const float* query = (const float*)d_in[0];
    const float* key   = (const float*)d_in[1];
    const float* value = (const float*)d_in[2];
    const float* Wq = (const float*)d_in[3];
    const float* bq = (const float*)d_in[4];
    const float* Wk = (const float*)d_in[5];
    const float* bk = (const float*)d_in[6];
    const float* Wv = (const float*)d_in[7];
    const float* bv = (const float*)d_in[8];
    const float* Wg = (const float*)d_in[9];
    const float* bg = (const float*)d_in[10];
    const float* Wo = (const float*)d_in[11];
    const float* bo = (const float*)d_in[12];
    float* out = (float*)d_out;

    build_tables<<<(NP*32)/256, 256>>>();
    convert_in<<<dim3((MT*EP)/1024, 3), 256>>>(query, key, value);
    convert_w<<<dim3((EP*EP)/1024, 5), 256>>>(Wq, Wk, Wv, Wg, Wo);

    cudaFuncSetAttribute(qkvg_kernel, cudaFuncAttributeMaxDynamicSharedMemorySize, PROJ_SMEM);
    cudaFuncSetAttribute(out_kernel,  cudaFuncAttributeMaxDynamicSharedMemorySize, PROJ_SMEM);
    cudaFuncSetAttribute(retention_kernel, cudaFuncAttributeMaxDynamicSharedMemorySize, (int)RET_SMEM);

    qkvg_kernel<<<dim3(4, 32, 4), 256, PROJ_SMEM>>>(bq, bk, bv, bg);
    retention_kernel<<<dim3(16, 8, 2), 256, RET_SMEM>>>();
    out_kernel<<<dim3(4, 32, 1), 256, PROJ_SMEM>>>(bo, out);
}

// round 5
// speedup vs baseline: 2.6047x; 1.1673x over previous
#include <cuda_runtime.h>
#include <cuda_bf16.h>
#include <math.h>
#include <stdint.h>

#define NP 2048
#define EP 512
#define MT 4096

// ---------------- device scratch ----------------
__device__ __align__(16) float g_sin[NP*32];
__device__ __align__(16) float g_cos[NP*32];
__device__ __align__(16) float g_scale[NP*32];
__device__ __align__(16) __nv_bfloat16 g_INh[3][MT*EP];
__device__ __align__(16) __nv_bfloat16 g_INl[3][MT*EP];
__device__ __align__(16) __nv_bfloat16 g_Wh[5][EP*EP];
__device__ __align__(16) __nv_bfloat16 g_Wl[5][EP*EP];
__device__ __align__(16) __nv_bfloat16 g_Qh[MT*EP], g_Ql[MT*EP];
__device__ __align__(16) __nv_bfloat16 g_Kh[MT*EP], g_Kl[MT*EP];
__device__ __align__(16) __nv_bfloat16 g_Vh[MT*EP], g_Vl[MT*EP];
__device__ __align__(16) __nv_bfloat16 g_RGh[MT*EP], g_RGl[MT*EP];
__device__ __align__(16) float g_G[MT*EP];

// ---------------- helpers ----------------
__device__ __forceinline__ uint32_t smem_u32(const void* p) {
    uint32_t a;
    asm("{ .reg .u64 t; cvta.to.shared.u64 t, %1; cvt.u32.u64 %0, t; }" : "=r"(a) : "l"(p));
    return a;
}
__device__ __forceinline__ void ldsm4(uint32_t* r, uint32_t a) {
    asm volatile("ldmatrix.sync.aligned.m8n8.x4.shared.b16 {%0,%1,%2,%3}, [%4];"
        : "=r"(r[0]), "=r"(r[1]), "=r"(r[2]), "=r"(r[3]) : "r"(a));
}
__device__ __forceinline__ void ldsm4t(uint32_t* r, uint32_t a) {
    asm volatile("ldmatrix.sync.aligned.m8n8.x4.trans.shared.b16 {%0,%1,%2,%3}, [%4];"
        : "=r"(r[0]), "=r"(r[1]), "=r"(r[2]), "=r"(r[3]) : "r"(a));
}
__device__ __forceinline__ void mma_bf16(float* c, const uint32_t* a, uint32_t b0, uint32_t b1) {
    asm volatile("mma.sync.aligned.m16n8k16.row.col.f32.bf16.bf16.f32 "
        "{%0,%1,%2,%3}, {%4,%5,%6,%7}, {%8,%9}, {%0,%1,%2,%3};"
        : "+f"(c[0]), "+f"(c[1]), "+f"(c[2]), "+f"(c[3])
        : "r"(a[0]), "r"(a[1]), "r"(a[2]), "r"(a[3]), "r"(b0), "r"(b1));
}
__device__ __forceinline__ void split_pair(float v0, float v1, uint32_t& hi, uint32_t& lo) {
    __nv_bfloat16 h0 = __float2bfloat16_rn(v0);
    __nv_bfloat16 h1 = __float2bfloat16_rn(v1);
    __nv_bfloat16 l0 = __float2bfloat16_rn(v0 - __bfloat162float(h0));
    __nv_bfloat16 l1 = __float2bfloat16_rn(v1 - __bfloat162float(h1));
    __nv_bfloat162 H = __halves2bfloat162(h0, h1);
    __nv_bfloat162 L = __halves2bfloat162(l0, l1);
    hi = *reinterpret_cast<uint32_t*>(&H);
    lo = *reinterpret_cast<uint32_t*>(&L);
}
__device__ __forceinline__ void cp16(uint32_t sdst, const void* gsrc) {
    asm volatile("cp.async.cg.shared.global [%0], [%1], 16;" :: "r"(sdst), "l"(gsrc) : "memory");
}
#define CP_COMMIT() asm volatile("cp.async.commit_group;" ::: "memory")
#define CP_WAIT(N)  asm volatile("cp.async.wait_group %0;" :: "n"(N) : "memory")

// ---------------- xpos tables ----------------
__global__ void build_tables() {
    int idx = blockIdx.x * 256 + threadIdx.x;
    if (idx >= NP*32) return;
    int n = idx >> 5, j = idx & 31;
    float inv_freq = expf(-(float)j * (9.210340371976184f / 32.f));
    float s, c;
    sincosf((float)n * inv_freq, &s, &c);
    float xscale = (2.f*(float)j + 25.6f) / 89.6f;
    float power = ((float)n - 1024.f) * (1.f/512.f);
    g_sin[idx] = s; g_cos[idx] = c; g_scale[idx] = expf(power * logf(xscale));
}

// ---------------- hi/lo pre-split ----------------
__global__ void convert_in(const float* __restrict__ q, const float* __restrict__ k,
                           const float* __restrict__ v) {
    int z = blockIdx.y;
    const float* src = (z == 0) ? q : (z == 1) ? k : v;
    int idx = (blockIdx.x * 256 + threadIdx.x) * 4;
    float4 x = *(const float4*)(src + idx);
    uint32_t h0,l0,h1,l1;
    split_pair(x.x, x.y, h0, l0);
    split_pair(x.z, x.w, h1, l1);
    *(uint2*)(&g_INh[z][idx]) = make_uint2(h0, h1);
    *(uint2*)(&g_INl[z][idx]) = make_uint2(l0, l1);
}
__global__ void convert_w(const float* __restrict__ w0, const float* __restrict__ w1,
                          const float* __restrict__ w2, const float* __restrict__ w3,
                          const float* __restrict__ w4) {
    int z = blockIdx.y;
    const float* src = (z == 0) ? w0 : (z == 1) ? w1 : (z == 2) ? w2 : (z == 3) ? w3 : w4;
    int idx = (blockIdx.x * 256 + threadIdx.x) * 4;
    float4 x = *(const float4*)(src + idx);
    uint32_t h0,l0,h1,l1;
    split_pair(x.x, x.y, h0, l0);
    split_pair(x.z, x.w, h1, l1);
    *(uint2*)(&g_Wh[z][idx]) = make_uint2(h0, h1);
    *(uint2*)(&g_Wl[z][idx]) = make_uint2(l0, l1);
}

// ================= projection GEMM (bf16x3, cp.async 3-stage) =================
// stage buffer 40960B: AH@0 AL@10240 BH@20480 BL@30720; row stride 80B.
#define PROJ_SMEM (3*40960)

__device__ __forceinline__ void proj_load_stage(
    uint32_t sb, int stage,
    const __nv_bfloat16* __restrict__ Ah, const __nv_bfloat16* __restrict__ Al,
    const __nv_bfloat16* __restrict__ Bh, const __nv_bfloat16* __restrict__ Bl,
    int m0, int n0, int kc, int tid)
{
    uint32_t s0 = sb + stage * 40960;
    #pragma unroll
    for (int i = 0; i < 2; i++) {
        int t = tid + i*256; int row = t >> 2, seg = t & 3;
        uint32_t so = (uint32_t)row*80 + seg*16;
        size_t ga = (size_t)(m0 + row)*EP + kc*32 + seg*8;
        size_t gb = (size_t)(n0 + row)*EP + kc*32 + seg*8;
        cp16(s0 +          so, Ah + ga);
        cp16(s0 + 10240 +  so, Al + ga);
        cp16(s0 + 20480 +  so, Bh + gb);
        cp16(s0 + 30720 +  so, Bl + gb);
    }
}

__device__ __forceinline__ void proj_body(
    const __nv_bfloat16* __restrict__ Ah, const __nv_bfloat16* __restrict__ Al,
    const __nv_bfloat16* __restrict__ Bh, const __nv_bfloat16* __restrict__ Bl,
    const float* __restrict__ bias, int epi,
    float* Cf, __nv_bfloat16* Ch, __nv_bfloat16* Cl, char* sm)
{
    const int tid = threadIdx.x, lane = tid & 31, wid = tid >> 5;
    const int wm = wid & 3, wn = wid >> 2;
    const int n0 = blockIdx.x * 128, m0 = blockIdx.y * 128;
    const uint32_t sb = smem_u32(sm);
    float acc[2][8][4] = {};

    proj_load_stage(sb, 0, Ah, Al, Bh, Bl, m0, n0, 0, tid); CP_COMMIT();
    proj_load_stage(sb, 1, Ah, Al, Bh, Bl, m0, n0, 1, tid); CP_COMMIT();

    for (int kc = 0; kc < 16; kc++) {
        CP_WAIT(1);
        __syncthreads();
        if (kc + 2 < 16)
            proj_load_stage(sb, (kc + 2) % 3, Ah, Al, Bh, Bl, m0, n0, kc + 2, tid);
        CP_COMMIT();

        const uint32_t base = sb + (kc % 3) * 40960;
        #pragma unroll
        for (int kk = 0; kk < 2; kk++) {
            uint32_t ah[2][4], al[2][4];
            #pragma unroll
            for (int mt = 0; mt < 2; mt++) {
                uint32_t off = (uint32_t)(wm*32 + mt*16 + (lane & 15))*80 + kk*32 + ((lane >> 4) & 1)*16;
                ldsm4(ah[mt], base + off);
                ldsm4(al[mt], base + 10240 + off);
            }
            uint32_t bh[4][4], bl[4][4];
            #pragma unroll
            for (int jt = 0; jt < 4; jt++) {
                uint32_t off = (uint32_t)(wn*64 + jt*16 + (lane & 7) + ((lane & 16) ? 8 : 0))*80
                             + kk*32 + ((lane & 8) ? 16 : 0);
                ldsm4(bh[jt], base + 20480 + off);
                ldsm4(bl[jt], base + 30720 + off);
            }
            #pragma unroll
            for (int mt = 0; mt < 2; mt++)
                #pragma unroll
                for (int nt = 0; nt < 8; nt++) {
                    int jt = nt >> 1, o = (nt & 1)*2;
                    mma_bf16(acc[mt][nt], ah[mt], bh[jt][o], bh[jt][o+1]);
                    mma_bf16(acc[mt][nt], ah[mt], bl[jt][o], bl[jt][o+1]);
                    mma_bf16(acc[mt][nt], al[mt], bh[jt][o], bh[jt][o+1]);
                }
        }
    }

    #pragma unroll
    for (int mt = 0; mt < 2; mt++) {
        #pragma unroll
        for (int rr = 0; rr < 2; rr++) {
            int row = m0 + wm*32 + mt*16 + (lane >> 2) + rr*8;
            int npos = row & (NP - 1);
            #pragma unroll
            for (int nt = 0; nt < 8; nt++) {
                int col = n0 + wn*64 + nt*8 + 2*(lane & 3);
                float x0 = acc[mt][nt][rr*2]     + bias[col];
                float x1 = acc[mt][nt][rr*2 + 1] + bias[col + 1];
                if (epi == 1) {
                    x0 = x0 / (1.f + expf(-x0));
                    x1 = x1 / (1.f + expf(-x1));
                } else if (epi == 2 || epi == 3) {
                    int j2 = (col & 63) >> 1;
                    float sn = g_sin[npos*32 + j2];
                    float cs = g_cos[npos*32 + j2];
                    float sc = g_scale[npos*32 + j2];
                    if (epi == 3) sc = 1.f / sc;
                    float s = sn * sc, c = cs * sc;
                    float y0 = x0 * c - x1 * s;
                    float y1 = x1 * c + x0 * s;
                    if (epi == 3) { y0 *= 0.125f; y1 *= 0.125f; }
                    x0 = y0; x1 = y1;
                }
                size_t off = (size_t)row*EP + col;
                if (Ch) {
                    uint32_t hh, ll;
                    split_pair(x0, x1, hh, ll);
                    *(uint32_t*)(Ch + off) = hh;
                    *(uint32_t*)(Cl + off) = ll;
                } else {
                    *(float2*)(Cf + off) = make_float2(x0, x1);
                }
            }
        }
    }
}

__global__ void __launch_bounds__(256) qkvg_kernel(
    const float* __restrict__ bq, const float* __restrict__ bk,
    const float* __restrict__ bv, const float* __restrict__ bg)
{
    extern __shared__ char sm[];
    const int z = blockIdx.z;
    const __nv_bfloat16* Ah = g_INh[(z == 3) ? 0 : z];
    const __nv_bfloat16* Al = g_INl[(z == 3) ? 0 : z];
    const float* bias = (z == 0) ? bq : (z == 1) ? bk : (z == 2) ? bv : bg;
    __nv_bfloat16* Ch = (z == 0) ? g_Qh : (z == 1) ? g_Kh : (z == 2) ? g_Vh : (__nv_bfloat16*)0;
    __nv_bfloat16* Cl = (z == 0) ? g_Ql : (z == 1) ? g_Kl : (z == 2) ? g_Vl : (__nv_bfloat16*)0;
    float* Cf = (z == 3) ? g_G : (float*)0;
    const int epi = (z == 0) ? 2 : (z == 1) ? 3 : (z == 2) ? 0 : 1;
    proj_body(Ah, Al, g_Wh[z], g_Wl[z], bias, epi, Cf, Ch, Cl, sm);
}

__global__ void __launch_bounds__(256) out_kernel(const float* __restrict__ bo,
                                                  float* __restrict__ out)
{
    extern __shared__ char sm[];
    proj_body(g_RGh, g_RGl, g_Wh[4], g_Wl[4], bo, 0, out, (__nv_bfloat16*)0, (__nv_bfloat16*)0, sm);
}

// ================= retention (bf16x3, paired q-tiles, cp.async K/V) =================
// smem: QH 0 QL 18432 | KV stage s @ 36864+s*36864 {KH+0 KL+9216 VH+18432 VL+27648}
//       SH 110592 SL 129024 ; total 147456
#define RSM_QH 0u
#define RSM_QL 18432u
#define RSM_KV 36864u
#define RSM_SH 110592u
#define RSM_SL 129024u
#define RET_SMEM 147456u

__device__ __forceinline__ void kv_load_stage(uint32_t sb, int stage, int b, int h,
                                              int st, int tid)
{
    uint32_t s0 = sb + RSM_KV + (uint32_t)stage * 36864u;
    #pragma unroll
    for (int i = 0; i < 2; i++) {
        int t = tid + i*256; int row = t >> 3, seg = t & 7;
        uint32_t so = (uint32_t)row*144 + seg*16;
        size_t ga = (size_t)(b*NP + st*64 + row)*EP + h*64 + seg*8;
        cp16(s0 +          so, g_Kh + ga);
        cp16(s0 + 9216 +   so, g_Kl + ga);
        cp16(s0 + 18432 +  so, g_Vh + ga);
        cp16(s0 + 27648 +  so, g_Vl + ga);
    }
}

__global__ void __launch_bounds__(256, 1) retention_kernel()
{
    extern __shared__ char sm[];
    const int tid = threadIdx.x, lane = tid & 31, wid = tid >> 5;
    const int h = blockIdx.y, b = blockIdx.z;
    const uint32_t sb = smem_u32(sm);

    const float gamma = 1.f - expf(-(3.465735902799726f + 0.396084103177426f * (float)h));
    const float l2g = log2f(gamma);

    float colf[16];
    #pragma unroll
    for (int nt = 0; nt < 8; nt++) {
        int sl = nt*8 + 2*(lane & 3);
        colf[nt*2]   = exp2f(-l2g * (float)sl);
        colf[nt*2+1] = exp2f(-l2g * (float)(sl + 1));
    }
    const int nl0 = wid*16 + (lane >> 2);
    const uint32_t swh = sb + RSM_SH + wid*2304;
    const uint32_t swl = sb + RSM_SL + wid*2304;

    for (int phase = 0; phase < 2; phase++) {
        const int qt = phase ? (int)blockIdx.x : 15 - (int)blockIdx.x;

        // load Q tile (128 x 64, hi/lo)
        #pragma unroll
        for (int i = 0; i < 4; i++) {
            int t = tid + i*256; int row = t >> 3, seg = t & 7;
            size_t ga = (size_t)(b*NP + qt*128 + row)*EP + h*64 + seg*8;
            *(uint4*)(sm + RSM_QH + row*144 + seg*16) = *(const uint4*)(g_Qh + ga);
            *(uint4*)(sm + RSM_QL + row*144 + seg*16) = *(const uint4*)(g_Ql + ga);
        }
        __syncthreads();   // prev-phase compute done + Q visible

        kv_load_stage(sb, 0, b, h, 0, tid); CP_COMMIT();

        uint32_t qh[4][4], ql[4][4];
        #pragma unroll
        for (int kk = 0; kk < 4; kk++) {
            uint32_t off = (uint32_t)(wid*16 + (lane & 15))*144 + kk*32 + ((lane >> 4) & 1)*16;
            ldsm4(qh[kk], sb + RSM_QH + off);
            ldsm4(ql[kk], sb + RSM_QL + off);
        }

        float ret[8][4] = {};
        const int n_st = 2*qt + 2;

        for (int st = 0; st < n_st; st++) {
            CP_WAIT(0);
            __syncthreads();
            if (st + 1 < n_st) kv_load_stage(sb, (st + 1) & 1, b, h, st + 1, tid);
            CP_COMMIT();

            const uint32_t kvb = sb + RSM_KV + (uint32_t)(st & 1) * 36864u;

            // gemm1: sim = Q K^T (k = 64)
            float simf[8][4] = {};
            #pragma unroll
            for (int kk = 0; kk < 4; kk++) {
                uint32_t bh[4][4], bl[4][4];
                #pragma unroll
                for (int jt = 0; jt < 4; jt++) {
                    uint32_t off = (uint32_t)(jt*16 + (lane & 7) + ((lane & 16) ? 8 : 0))*144
                                 + kk*32 + ((lane & 8) ? 16 : 0);
                    ldsm4(bh[jt], kvb + off);
                    ldsm4(bl[jt], kvb + 9216 + off);
                }
                #pragma unroll
                for (int nt = 0; nt < 8; nt++) {
                    int jt = nt >> 1, o = (nt & 1)*2;
                    mma_bf16(simf[nt], qh[kk], bh[jt][o], bh[jt][o+1]);
                    mma_bf16(simf[nt], qh[kk], bl[jt][o], bl[jt][o+1]);
                    mma_bf16(simf[nt], ql[kk], bh[jt][o], bh[jt][o+1]);
                }
            }

            // decay + mask + split -> warp-private S buffer
            const int db = qt*128 - st*64;
            const float brf0 = exp2f(l2g * (float)(db + nl0));
            const float brf1 = exp2f(l2g * (float)(db + nl0 + 8));
            #pragma unroll
            for (int nt = 0; nt < 8; nt++) {
                int sl0 = nt*8 + 2*(lane & 3);
                float v00 = (db + nl0 - sl0     >= 0) ? simf[nt][0]*brf0*colf[nt*2]   : 0.f;
                float v01 = (db + nl0 - sl0 - 1 >= 0) ? simf[nt][1]*brf0*colf[nt*2+1] : 0.f;
                float v10 = (db + nl0 + 8 - sl0     >= 0) ? simf[nt][2]*brf1*colf[nt*2]   : 0.f;
                float v11 = (db + nl0 + 8 - sl0 - 1 >= 0) ? simf[nt][3]*brf1*colf[nt*2+1] : 0.f;
                uint32_t hh, ll;
                uint32_t so0 = (uint32_t)(lane >> 2)*144 + sl0*2;
                split_pair(v00, v01, hh, ll);
                *(uint32_t*)(sm + RSM_SH + wid*2304 + so0) = hh;
                *(uint32_t*)(sm + RSM_SL + wid*2304 + so0) = ll;
                split_pair(v10, v11, hh, ll);
                *(uint32_t*)(sm + RSM_SH + wid*2304 + so0 + 8*144) = hh;
                *(uint32_t*)(sm + RSM_SL + wid*2304 + so0 + 8*144) = ll;
            }
            __syncwarp();

            // gemm2: ret += sim @ V
            #pragma unroll
            for (int kk = 0; kk < 4; kk++) {
                uint32_t ah2[4], al2[4];
                uint32_t aoff = (uint32_t)(lane & 15)*144 + kk*32 + ((lane >> 4) & 1)*16;
                ldsm4(ah2, swh + aoff);
                ldsm4(al2, swl + aoff);
                uint32_t bh[4][4], bl[4][4];
                #pragma unroll
                for (int dt = 0; dt < 4; dt++) {
                    uint32_t off = (uint32_t)(kk*16 + (lane & 15))*144 + dt*32 + ((lane >> 4) & 1)*16;
                    ldsm4t(bh[dt], kvb + 18432 + off);
                    ldsm4t(bl[dt], kvb + 27648 + off);
                }
                #pragma unroll
                for (int nt = 0; nt < 8; nt++) {
                    int dt = nt >> 1, o = (nt & 1)*2;
                    mma_bf16(ret[nt], ah2, bh[dt][o], bh[dt][o+1]);
                    mma_bf16(ret[nt], ah2, bl[dt][o], bl[dt][o+1]);
                    mma_bf16(ret[nt], al2, bh[dt][o], bh[dt][o+1]);
                }
            }
            __syncwarp();
        }

        // groupnorm + gate + write hi/lo planes
        #pragma unroll
        for (int rr = 0; rr < 2; rr++) {
            float s1 = 0.f, s2 = 0.f;
            #pragma unroll
            for (int nt = 0; nt < 8; nt++) {
                float a = ret[nt][rr*2], c = ret[nt][rr*2+1];
                s1 += a + c; s2 += a*a + c*c;
            }
            s1 += __shfl_xor_sync(0xffffffffu, s1, 1); s2 += __shfl_xor_sync(0xffffffffu, s2, 1);
            s1 += __shfl_xor_sync(0xffffffffu, s1, 2); s2 += __shfl_xor_sync(0xffffffffu, s2, 2);
            float mean = s1 * (1.f/64.f);
            float var  = s2 * (1.f/64.f) - mean*mean;
            float inv  = rsqrtf(var + 1e-6f);
            int row = qt*128 + nl0 + rr*8;
            size_t base = (size_t)(b*NP + row)*EP + h*64;
            #pragma unroll
            for (int nt = 0; nt < 8; nt++) {
                int col = nt*8 + 2*(lane & 3);
                float2 g2 = *(const float2*)(g_G + base + col);
                float x0 = (ret[nt][rr*2]   - mean)*inv * g2.x;
                float x1 = (ret[nt][rr*2+1] - mean)*inv * g2.y;
                uint32_t hh, ll;
                split_pair(x0, x1, hh, ll);
                *(uint32_t*)(g_RGh + base + col) = hh;
                *(uint32_t*)(g_RGl + base + col) = ll;
            }
        }
    }
}

// ---------------- launch ----------------
extern "C" void kernel_launch(void* const* d_in, const int* in_sizes, int n_in,
                              void* d_out, int out_size) {
    const float* query = (const float*)d_in[0];
    const float* key   = (const float*)d_in[1];
    const float* value = (const float*)d_in[2];
    const float* Wq = (const float*)d_in[3];
    const float* bq = (const float*)d_in[4];
    const float* Wk = (const float*)d_in[5];
    const float* bk = (const float*)d_in[6];
    const float* Wv = (const float*)d_in[7];
    const float* bv = (const float*)d_in[8];
    const float* Wg = (const float*)d_in[9];
    const float* bg = (const float*)d_in[10];
    const float* Wo = (const float*)d_in[11];
    const float* bo = (const float*)d_in[12];
    float* out = (float*)d_out;

    build_tables<<<(NP*32)/256, 256>>>();
    convert_in<<<dim3((MT*EP)/1024, 3), 256>>>(query, key, value);
    convert_w<<<dim3((EP*EP)/1024, 5), 256>>>(Wq, Wk, Wv, Wg, Wo);

    cudaFuncSetAttribute(qkvg_kernel, cudaFuncAttributeMaxDynamicSharedMemorySize, PROJ_SMEM);
    cudaFuncSetAttribute(out_kernel,  cudaFuncAttributeMaxDynamicSharedMemorySize, PROJ_SMEM);
    cudaFuncSetAttribute(retention_kernel, cudaFuncAttributeMaxDynamicSharedMemorySize, (int)RET_SMEM);

    qkvg_kernel<<<dim3(4, 32, 4), 256, PROJ_SMEM>>>(bq, bk, bv, bg);
    retention_kernel<<<dim3(8, 8, 2), 256, RET_SMEM>>>();
    out_kernel<<<dim3(4, 32, 1), 256, PROJ_SMEM>>>(bo, out);
}

// round 7
// speedup vs baseline: 2.8067x; 1.0776x over previous
#include <cuda_runtime.h>
#include <cuda_bf16.h>
#include <math.h>
#include <stdint.h>

#define NP 2048
#define EP 512
#define MT 4096

// ---------------- device scratch ----------------
__device__ __align__(16) float g_sin[NP*32];
__device__ __align__(16) float g_cos[NP*32];
__device__ __align__(16) float g_scale[NP*32];
__device__ __align__(16) __nv_bfloat16 g_INh[3][MT*EP];
__device__ __align__(16) __nv_bfloat16 g_INl[3][MT*EP];
__device__ __align__(16) __nv_bfloat16 g_Wh[5][EP*EP];
__device__ __align__(16) __nv_bfloat16 g_Wl[5][EP*EP];
__device__ __align__(16) __nv_bfloat16 g_Qh[MT*EP], g_Ql[MT*EP];
__device__ __align__(16) __nv_bfloat16 g_Kh[MT*EP], g_Kl[MT*EP];
__device__ __align__(16) __nv_bfloat16 g_Vh[MT*EP], g_Vl[MT*EP];
__device__ __align__(16) __nv_bfloat16 g_RGh[MT*EP], g_RGl[MT*EP];
__device__ __align__(16) float g_G[MT*EP];

// ---------------- helpers ----------------
__device__ __forceinline__ uint32_t smem_u32(const void* p) {
    uint32_t a;
    asm("{ .reg .u64 t; cvta.to.shared.u64 t, %1; cvt.u32.u64 %0, t; }" : "=r"(a) : "l"(p));
    return a;
}
__device__ __forceinline__ void ldsm4(uint32_t* r, uint32_t a) {
    asm volatile("ldmatrix.sync.aligned.m8n8.x4.shared.b16 {%0,%1,%2,%3}, [%4];"
        : "=r"(r[0]), "=r"(r[1]), "=r"(r[2]), "=r"(r[3]) : "r"(a));
}
__device__ __forceinline__ void ldsm4t(uint32_t* r, uint32_t a) {
    asm volatile("ldmatrix.sync.aligned.m8n8.x4.trans.shared.b16 {%0,%1,%2,%3}, [%4];"
        : "=r"(r[0]), "=r"(r[1]), "=r"(r[2]), "=r"(r[3]) : "r"(a));
}
__device__ __forceinline__ void mma_bf16(float* c, const uint32_t* a, uint32_t b0, uint32_t b1) {
    asm volatile("mma.sync.aligned.m16n8k16.row.col.f32.bf16.bf16.f32 "
        "{%0,%1,%2,%3}, {%4,%5,%6,%7}, {%8,%9}, {%0,%1,%2,%3};"
        : "+f"(c[0]), "+f"(c[1]), "+f"(c[2]), "+f"(c[3])
        : "r"(a[0]), "r"(a[1]), "r"(a[2]), "r"(a[3]), "r"(b0), "r"(b1));
}
__device__ __forceinline__ void split_pair(float v0, float v1, uint32_t& hi, uint32_t& lo) {
    __nv_bfloat16 h0 = __float2bfloat16_rn(v0);
    __nv_bfloat16 h1 = __float2bfloat16_rn(v1);
    __nv_bfloat16 l0 = __float2bfloat16_rn(v0 - __bfloat162float(h0));
    __nv_bfloat16 l1 = __float2bfloat16_rn(v1 - __bfloat162float(h1));
    __nv_bfloat162 H = __halves2bfloat162(h0, h1);
    __nv_bfloat162 L = __halves2bfloat162(l0, l1);
    hi = *reinterpret_cast<uint32_t*>(&H);
    lo = *reinterpret_cast<uint32_t*>(&L);
}
__device__ __forceinline__ void cp16(uint32_t sdst, const void* gsrc) {
    asm volatile("cp.async.cg.shared.global [%0], [%1], 16;" :: "r"(sdst), "l"(gsrc) : "memory");
}
#define CP_COMMIT() asm volatile("cp.async.commit_group;" ::: "memory")
#define CP_WAIT(N)  asm volatile("cp.async.wait_group %0;" :: "n"(N) : "memory")

// ---------------- xpos tables ----------------
__global__ void build_tables() {
    int idx = blockIdx.x * 256 + threadIdx.x;
    if (idx >= NP*32) return;
    int n = idx >> 5, j = idx & 31;
    float inv_freq = expf(-(float)j * (9.210340371976184f / 32.f));
    float s, c;
    sincosf((float)n * inv_freq, &s, &c);
    float xscale = (2.f*(float)j + 25.6f) / 89.6f;
    float power = ((float)n - 1024.f) * (1.f/512.f);
    g_sin[idx] = s; g_cos[idx] = c; g_scale[idx] = expf(power * logf(xscale));
}

// ---------------- hi/lo pre-split ----------------
__global__ void convert_in(const float* __restrict__ q, const float* __restrict__ k,
                           const float* __restrict__ v) {
    int z = blockIdx.y;
    const float* src = (z == 0) ? q : (z == 1) ? k : v;
    int idx = (blockIdx.x * 256 + threadIdx.x) * 4;
    float4 x = *(const float4*)(src + idx);
    uint32_t h0,l0,h1,l1;
    split_pair(x.x, x.y, h0, l0);
    split_pair(x.z, x.w, h1, l1);
    *(uint2*)(&g_INh[z][idx]) = make_uint2(h0, h1);
    *(uint2*)(&g_INl[z][idx]) = make_uint2(l0, l1);
}
__global__ void convert_w(const float* __restrict__ w0, const float* __restrict__ w1,
                          const float* __restrict__ w2, const float* __restrict__ w3,
                          const float* __restrict__ w4) {
    int z = blockIdx.y;
    const float* src = (z == 0) ? w0 : (z == 1) ? w1 : (z == 2) ? w2 : (z == 3) ? w3 : w4;
    int idx = (blockIdx.x * 256 + threadIdx.x) * 4;
    float4 x = *(const float4*)(src + idx);
    uint32_t h0,l0,h1,l1;
    split_pair(x.x, x.y, h0, l0);
    split_pair(x.z, x.w, h1, l1);
    *(uint2*)(&g_Wh[z][idx]) = make_uint2(h0, h1);
    *(uint2*)(&g_Wl[z][idx]) = make_uint2(l0, l1);
}

// ================= projection GEMM (bf16x3, 4-stage K16 chunks, 2 CTA/SM) ========
// stage 24576B: AH@0 AL@6144 BH@12288 BL@18432; row stride 48B (16 bf16 + pad).
#define PSTG 24576
#define PROJ_SMEM (4*PSTG)

__device__ __forceinline__ void proj_load_stage(
    uint32_t sb, int stage,
    const __nv_bfloat16* __restrict__ Ah, const __nv_bfloat16* __restrict__ Al,
    const __nv_bfloat16* __restrict__ Bh, const __nv_bfloat16* __restrict__ Bl,
    int m0, int n0, int kc, int tid)
{
    uint32_t s0 = sb + stage * PSTG;
    int row = tid >> 1, seg = tid & 1;
    uint32_t so = (uint32_t)row*48 + seg*16;
    size_t ga = (size_t)(m0 + row)*EP + kc*16 + seg*8;
    size_t gb = (size_t)(n0 + row)*EP + kc*16 + seg*8;
    cp16(s0 +          so, Ah + ga);
    cp16(s0 + 6144 +   so, Al + ga);
    cp16(s0 + 12288 +  so, Bh + gb);
    cp16(s0 + 18432 +  so, Bl + gb);
}

__device__ __forceinline__ void proj_body(
    const __nv_bfloat16* __restrict__ Ah, const __nv_bfloat16* __restrict__ Al,
    const __nv_bfloat16* __restrict__ Bh, const __nv_bfloat16* __restrict__ Bl,
    const float* __restrict__ bias, int epi,
    float* Cf, __nv_bfloat16* Ch, __nv_bfloat16* Cl, char* sm)
{
    const int tid = threadIdx.x, lane = tid & 31, wid = tid >> 5;
    const int wm = wid & 3, wn = wid >> 2;
    const int n0 = blockIdx.x * 128, m0 = blockIdx.y * 128;
    const uint32_t sb = smem_u32(sm);
    float acc[2][8][4] = {};

    proj_load_stage(sb, 0, Ah, Al, Bh, Bl, m0, n0, 0, tid); CP_COMMIT();
    proj_load_stage(sb, 1, Ah, Al, Bh, Bl, m0, n0, 1, tid); CP_COMMIT();
    proj_load_stage(sb, 2, Ah, Al, Bh, Bl, m0, n0, 2, tid); CP_COMMIT();

    for (int kc = 0; kc < 32; kc++) {
        CP_WAIT(2);
        __syncthreads();
        if (kc + 3 < 32)
            proj_load_stage(sb, (kc + 3) & 3, Ah, Al, Bh, Bl, m0, n0, kc + 3, tid);
        CP_COMMIT();

        const uint32_t base = sb + (kc & 3) * PSTG;
        uint32_t ah[2][4], al[2][4];
        #pragma unroll
        for (int mt = 0; mt < 2; mt++) {
            uint32_t off = (uint32_t)(wm*32 + mt*16 + (lane & 15))*48 + ((lane >> 4) & 1)*16;
            ldsm4(ah[mt], base + off);
            ldsm4(al[mt], base + 6144 + off);
        }
        #pragma unroll
        for (int jh = 0; jh < 2; jh++) {
            uint32_t bh[2][4], bl[2][4];
            #pragma unroll
            for (int j = 0; j < 2; j++) {
                int jt = jh*2 + j;
                uint32_t off = (uint32_t)(wn*64 + jt*16 + (lane & 7) + ((lane & 16) ? 8 : 0))*48
                             + ((lane & 8) ? 16 : 0);
                ldsm4(bh[j], base + 12288 + off);
                ldsm4(bl[j], base + 18432 + off);
            }
            #pragma unroll
            for (int mt = 0; mt < 2; mt++)
                #pragma unroll
                for (int nn = 0; nn < 4; nn++) {
                    int nt = jh*4 + nn;
                    int j = nn >> 1, o = (nn & 1)*2;
                    mma_bf16(acc[mt][nt], ah[mt], bh[j][o], bh[j][o+1]);
                    mma_bf16(acc[mt][nt], ah[mt], bl[j][o], bl[j][o+1]);
                    mma_bf16(acc[mt][nt], al[mt], bh[j][o], bh[j][o+1]);
                }
        }
    }

    #pragma unroll
    for (int mt = 0; mt < 2; mt++) {
        #pragma unroll
        for (int rr = 0; rr < 2; rr++) {
            int row = m0 + wm*32 + mt*16 + (lane >> 2) + rr*8;
            int npos = row & (NP - 1);
            #pragma unroll
            for (int nt = 0; nt < 8; nt++) {
                int col = n0 + wn*64 + nt*8 + 2*(lane & 3);
                float x0 = acc[mt][nt][rr*2]     + bias[col];
                float x1 = acc[mt][nt][rr*2 + 1] + bias[col + 1];
                if (epi == 1) {
                    x0 = x0 / (1.f + expf(-x0));
                    x1 = x1 / (1.f + expf(-x1));
                } else if (epi == 2 || epi == 3) {
                    int j2 = (col & 63) >> 1;
                    float sn = g_sin[npos*32 + j2];
                    float cs = g_cos[npos*32 + j2];
                    float sc = g_scale[npos*32 + j2];
                    if (epi == 3) sc = 1.f / sc;
                    float s = sn * sc, c = cs * sc;
                    float y0 = x0 * c - x1 * s;
                    float y1 = x1 * c + x0 * s;
                    if (epi == 3) { y0 *= 0.125f; y1 *= 0.125f; }
                    x0 = y0; x1 = y1;
                }
                size_t off = (size_t)row*EP + col;
                if (Ch) {
                    uint32_t hh, ll;
                    split_pair(x0, x1, hh, ll);
                    *(uint32_t*)(Ch + off) = hh;
                    *(uint32_t*)(Cl + off) = ll;
                } else {
                    *(float2*)(Cf + off) = make_float2(x0, x1);
                }
            }
        }
    }
}

__global__ void __launch_bounds__(256, 2) qkvg_kernel(
    const float* __restrict__ bq, const float* __restrict__ bk,
    const float* __restrict__ bv, const float* __restrict__ bg)
{
    extern __shared__ char sm[];
    const int z = blockIdx.z;
    const __nv_bfloat16* Ah = g_INh[(z == 3) ? 0 : z];
    const __nv_bfloat16* Al = g_INl[(z == 3) ? 0 : z];
    const float* bias = (z == 0) ? bq : (z == 1) ? bk : (z == 2) ? bv : bg;
    __nv_bfloat16* Ch = (z == 0) ? g_Qh : (z == 1) ? g_Kh : (z == 2) ? g_Vh : (__nv_bfloat16*)0;
    __nv_bfloat16* Cl = (z == 0) ? g_Ql : (z == 1) ? g_Kl : (z == 2) ? g_Vl : (__nv_bfloat16*)0;
    float* Cf = (z == 3) ? g_G : (float*)0;
    const int epi = (z == 0) ? 2 : (z == 1) ? 3 : (z == 2) ? 0 : 1;
    proj_body(Ah, Al, g_Wh[z], g_Wl[z], bias, epi, Cf, Ch, Cl, sm);
}

__global__ void __launch_bounds__(256, 2) out_kernel(const float* __restrict__ bo,
                                                     float* __restrict__ out)
{
    extern __shared__ char sm[];
    proj_body(g_RGh, g_RGl, g_Wh[4], g_Wl[4], bo, 0, out, (__nv_bfloat16*)0, (__nv_bfloat16*)0, sm);
}

// ================= retention (bf16x3, S in registers, 4-stage KV ring) =================
// smem: QH 0 QL 18432 | KV stage s @ 36864 + s*36864 {KH+0 KL+9216 VH+18432 VL+27648}
// 4 stages so prefetch target (st+3)&3 never aliases the in-use buffer st&3.
#define RSM_QH 0u
#define RSM_QL 18432u
#define RSM_KV 36864u
#define RET_SMEM (36864u + 4u*36864u)   // 184320

__device__ __forceinline__ void kv_load_stage(uint32_t sb, int stage, int b, int h,
                                              int st, int tid)
{
    uint32_t s0 = sb + RSM_KV + (uint32_t)stage * 36864u;
    #pragma unroll
    for (int i = 0; i < 2; i++) {
        int t = tid + i*256; int row = t >> 3, seg = t & 7;
        uint32_t so = (uint32_t)row*144 + seg*16;
        size_t ga = (size_t)(b*NP + st*64 + row)*EP + h*64 + seg*8;
        cp16(s0 +          so, g_Kh + ga);
        cp16(s0 + 9216 +   so, g_Kl + ga);
        cp16(s0 + 18432 +  so, g_Vh + ga);
        cp16(s0 + 27648 +  so, g_Vl + ga);
    }
}

__global__ void __launch_bounds__(256, 1) retention_kernel()
{
    extern __shared__ char sm[];
    const int tid = threadIdx.x, lane = tid & 31, wid = tid >> 5;
    const int h = blockIdx.y, b = blockIdx.z;
    const uint32_t sb = smem_u32(sm);

    const float gamma = 1.f - expf(-(3.465735902799726f + 0.396084103177426f * (float)h));
    const float l2g = log2f(gamma);

    float colf[16];
    #pragma unroll
    for (int nt = 0; nt < 8; nt++) {
        int sl = nt*8 + 2*(lane & 3);
        colf[nt*2]   = exp2f(-l2g * (float)sl);
        colf[nt*2+1] = exp2f(-l2g * (float)(sl + 1));
    }
    const int nl0 = wid*16 + (lane >> 2);

    for (int phase = 0; phase < 2; phase++) {
        const int qt = phase ? (int)blockIdx.x : 15 - (int)blockIdx.x;
        const int n_st = 2*qt + 2;

        // load Q tile (128 x 64, hi/lo)
        #pragma unroll
        for (int i = 0; i < 4; i++) {
            int t = tid + i*256; int row = t >> 3, seg = t & 7;
            size_t ga = (size_t)(b*NP + qt*128 + row)*EP + h*64 + seg*8;
            *(uint4*)(sm + RSM_QH + row*144 + seg*16) = *(const uint4*)(g_Qh + ga);
            *(uint4*)(sm + RSM_QL + row*144 + seg*16) = *(const uint4*)(g_Ql + ga);
        }
        __syncthreads();   // prev-phase compute done + Q visible

        kv_load_stage(sb, 0, b, h, 0, tid); CP_COMMIT();
        if (n_st > 1) kv_load_stage(sb, 1, b, h, 1, tid);
        CP_COMMIT();
        if (n_st > 2) kv_load_stage(sb, 2, b, h, 2, tid);
        CP_COMMIT();

        uint32_t qh[4][4], ql[4][4];
        #pragma unroll
        for (int kk = 0; kk < 4; kk++) {
            uint32_t off = (uint32_t)(wid*16 + (lane & 15))*144 + kk*32 + ((lane >> 4) & 1)*16;
            ldsm4(qh[kk], sb + RSM_QH + off);
            ldsm4(ql[kk], sb + RSM_QL + off);
        }

        float ret[8][4] = {};

        for (int st = 0; st < n_st; st++) {
            CP_WAIT(2);
            __syncthreads();
            if (st + 3 < n_st) kv_load_stage(sb, (st + 3) & 3, b, h, st + 3, tid);
            CP_COMMIT();

            const uint32_t kvb = sb + RSM_KV + (uint32_t)(st & 3) * 36864u;

            // gemm1: sim = Q K^T (k = 64)
            float simf[8][4] = {};
            #pragma unroll
            for (int kk = 0; kk < 4; kk++) {
                uint32_t bh[4][4], bl[4][4];
                #pragma unroll
                for (int jt = 0; jt < 4; jt++) {
                    uint32_t off = (uint32_t)(jt*16 + (lane & 7) + ((lane & 16) ? 8 : 0))*144
                                 + kk*32 + ((lane & 8) ? 16 : 0);
                    ldsm4(bh[jt], kvb + off);
                    ldsm4(bl[jt], kvb + 9216 + off);
                }
                #pragma unroll
                for (int nt = 0; nt < 8; nt++) {
                    int jt = nt >> 1, o = (nt & 1)*2;
                    mma_bf16(simf[nt], qh[kk], bh[jt][o], bh[jt][o+1]);
                    mma_bf16(simf[nt], qh[kk], bl[jt][o], bl[jt][o+1]);
                    mma_bf16(simf[nt], ql[kk], bh[jt][o], bh[jt][o+1]);
                }
            }

            // decay + mask + split -> A-fragments of gemm2, all in registers.
            const int db = qt*128 - st*64;
            const float brf0 = exp2f(l2g * (float)(db + nl0));
            const float brf1 = exp2f(l2g * (float)(db + nl0 + 8));
            uint32_t pa_h[8], pa_l[8], pb_h[8], pb_l[8];
            #pragma unroll
            for (int nt = 0; nt < 8; nt++) {
                int sl0 = nt*8 + 2*(lane & 3);
                float v00 = (db + nl0 - sl0     >= 0) ? simf[nt][0]*brf0*colf[nt*2]   : 0.f;
                float v01 = (db + nl0 - sl0 - 1 >= 0) ? simf[nt][1]*brf0*colf[nt*2+1] : 0.f;
                float v10 = (db + nl0 + 8 - sl0     >= 0) ? simf[nt][2]*brf1*colf[nt*2]   : 0.f;
                float v11 = (db + nl0 + 8 - sl0 - 1 >= 0) ? simf[nt][3]*brf1*colf[nt*2+1] : 0.f;
                split_pair(v00, v01, pa_h[nt], pa_l[nt]);
                split_pair(v10, v11, pb_h[nt], pb_l[nt]);
            }

            // gemm2: ret += sim @ V (A fragments straight from registers)
            #pragma unroll
            for (int kk = 0; kk < 4; kk++) {
                uint32_t ah2[4] = { pa_h[2*kk], pb_h[2*kk], pa_h[2*kk+1], pb_h[2*kk+1] };
                uint32_t al2[4] = { pa_l[2*kk], pb_l[2*kk], pa_l[2*kk+1], pb_l[2*kk+1] };
                uint32_t bh[4][4], bl[4][4];
                #pragma unroll
                for (int dt = 0; dt < 4; dt++) {
                    uint32_t off = (uint32_t)(kk*16 + (lane & 15))*144 + dt*32 + ((lane >> 4) & 1)*16;
                    ldsm4t(bh[dt], kvb + 18432 + off);
                    ldsm4t(bl[dt], kvb + 27648 + off);
                }
                #pragma unroll
                for (int nt = 0; nt < 8; nt++) {
                    int dt = nt >> 1, o = (nt & 1)*2;
                    mma_bf16(ret[nt], ah2, bh[dt][o], bh[dt][o+1]);
                    mma_bf16(ret[nt], ah2, bl[dt][o], bl[dt][o+1]);
                    mma_bf16(ret[nt], al2, bh[dt][o], bh[dt][o+1]);
                }
            }
        }

        // groupnorm + gate + write hi/lo planes
        #pragma unroll
        for (int rr = 0; rr < 2; rr++) {
            float s1 = 0.f, s2 = 0.f;
            #pragma unroll
            for (int nt = 0; nt < 8; nt++) {
                float a = ret[nt][rr*2], c = ret[nt][rr*2+1];
                s1 += a + c; s2 += a*a + c*c;
            }
            s1 += __shfl_xor_sync(0xffffffffu, s1, 1); s2 += __shfl_xor_sync(0xffffffffu, s2, 1);
            s1 += __shfl_xor_sync(0xffffffffu, s1, 2); s2 += __shfl_xor_sync(0xffffffffu, s2, 2);
            float mean = s1 * (1.f/64.f);
            float var  = s2 * (1.f/64.f) - mean*mean;
            float inv  = rsqrtf(var + 1e-6f);
            int row = qt*128 + nl0 + rr*8;
            size_t base = (size_t)(b*NP + row)*EP + h*64;
            #pragma unroll
            for (int nt = 0; nt < 8; nt++) {
                int col = nt*8 + 2*(lane & 3);
                float2 g2 = *(const float2*)(g_G + base + col);
                float x0 = (ret[nt][rr*2]   - mean)*inv * g2.x;
                float x1 = (ret[nt][rr*2+1] - mean)*inv * g2.y;
                uint32_t hh, ll;
                split_pair(x0, x1, hh, ll);
                *(uint32_t*)(g_RGh + base + col) = hh;
                *(uint32_t*)(g_RGl + base + col) = ll;
            }
        }
    }
}

// ---------------- launch ----------------
extern "C" void kernel_launch(void* const* d_in, const int* in_sizes, int n_in,
                              void* d_out, int out_size) {
    const float* query = (const float*)d_in[0];
    const float* key   = (const float*)d_in[1];
    const float* value = (const float*)d_in[2];
    const float* Wq = (const float*)d_in[3];
    const float* bq = (const float*)d_in[4];
    const float* Wk = (const float*)d_in[5];
    const float* bk = (const float*)d_in[6];
    const float* Wv = (const float*)d_in[7];
    const float* bv = (const float*)d_in[8];
    const float* Wg = (const float*)d_in[9];
    const float* bg = (const float*)d_in[10];
    const float* Wo = (const float*)d_in[11];
    const float* bo = (const float*)d_in[12];
    float* out = (float*)d_out;

    build_tables<<<(NP*32)/256, 256>>>();
    convert_in<<<dim3((MT*EP)/1024, 3), 256>>>(query, key, value);
    convert_w<<<dim3((EP*EP)/1024, 5), 256>>>(Wq, Wk, Wv, Wg, Wo);

    cudaFuncSetAttribute(qkvg_kernel, cudaFuncAttributeMaxDynamicSharedMemorySize, PROJ_SMEM);
    cudaFuncSetAttribute(out_kernel,  cudaFuncAttributeMaxDynamicSharedMemorySize, PROJ_SMEM);
    cudaFuncSetAttribute(retention_kernel, cudaFuncAttributeMaxDynamicSharedMemorySize, (int)RET_SMEM);

    qkvg_kernel<<<dim3(4, 32, 4), 256, PROJ_SMEM>>>(bq, bk, bv, bg);
    retention_kernel<<<dim3(8, 8, 2), 256, RET_SMEM>>>();
    out_kernel<<<dim3(4, 32, 1), 256, PROJ_SMEM>>>(bo, out);
}

// round 8
// speedup vs baseline: 3.7545x; 1.3377x over previous
#include <cuda_runtime.h>
#include <cuda_fp16.h>
#include <math.h>
#include <stdint.h>

#define NP 2048
#define EP 512
#define MT 4096

// ---------------- device scratch ----------------
__device__ __align__(16) float g_sin[NP*32];
__device__ __align__(16) float g_cos[NP*32];
__device__ __align__(16) float g_scale[NP*32];
__device__ __align__(16) __half g_INh[3][MT*EP];
__device__ __align__(16) __half g_INl[3][MT*EP];
__device__ __align__(16) __half g_Wh[5][EP*EP];
__device__ __align__(16) __half g_Qh[MT*EP], g_Ql[MT*EP];
__device__ __align__(16) __half g_Kh[MT*EP];
__device__ __align__(16) __half g_Vh[MT*EP];
__device__ __align__(16) __half g_RGh[MT*EP], g_RGl[MT*EP];
__device__ __align__(16) float g_G[MT*EP];

// ---------------- helpers ----------------
__device__ __forceinline__ uint32_t smem_u32(const void* p) {
    uint32_t a;
    asm("{ .reg .u64 t; cvta.to.shared.u64 t, %1; cvt.u32.u64 %0, t; }" : "=r"(a) : "l"(p));
    return a;
}
__device__ __forceinline__ void ldsm4(uint32_t* r, uint32_t a) {
    asm volatile("ldmatrix.sync.aligned.m8n8.x4.shared.b16 {%0,%1,%2,%3}, [%4];"
        : "=r"(r[0]), "=r"(r[1]), "=r"(r[2]), "=r"(r[3]) : "r"(a));
}
__device__ __forceinline__ void ldsm4t(uint32_t* r, uint32_t a) {
    asm volatile("ldmatrix.sync.aligned.m8n8.x4.trans.shared.b16 {%0,%1,%2,%3}, [%4];"
        : "=r"(r[0]), "=r"(r[1]), "=r"(r[2]), "=r"(r[3]) : "r"(a));
}
__device__ __forceinline__ void mma_f16(float* c, const uint32_t* a, uint32_t b0, uint32_t b1) {
    asm volatile("mma.sync.aligned.m16n8k16.row.col.f32.f16.f16.f32 "
        "{%0,%1,%2,%3}, {%4,%5,%6,%7}, {%8,%9}, {%0,%1,%2,%3};"
        : "+f"(c[0]), "+f"(c[1]), "+f"(c[2]), "+f"(c[3])
        : "r"(a[0]), "r"(a[1]), "r"(a[2]), "r"(a[3]), "r"(b0), "r"(b1));
}
__device__ __forceinline__ void split_pair_h(float v0, float v1, uint32_t& hi, uint32_t& lo) {
    __half h0 = __float2half_rn(v0);
    __half h1 = __float2half_rn(v1);
    __half l0 = __float2half_rn(v0 - __half2float(h0));
    __half l1 = __float2half_rn(v1 - __half2float(h1));
    __half2 H = __halves2half2(h0, h1);
    __half2 L = __halves2half2(l0, l1);
    hi = *reinterpret_cast<uint32_t*>(&H);
    lo = *reinterpret_cast<uint32_t*>(&L);
}
__device__ __forceinline__ uint32_t pack_h(float v0, float v1) {
    __half2 H = __floats2half2_rn(v0, v1);
    return *reinterpret_cast<uint32_t*>(&H);
}
__device__ __forceinline__ void cp16(uint32_t sdst, const void* gsrc) {
    asm volatile("cp.async.cg.shared.global [%0], [%1], 16;" :: "r"(sdst), "l"(gsrc) : "memory");
}
#define CP_COMMIT() asm volatile("cp.async.commit_group;" ::: "memory")
#define CP_WAIT(N)  asm volatile("cp.async.wait_group %0;" :: "n"(N) : "memory")

// ---------------- xpos tables ----------------
__global__ void build_tables() {
    int idx = blockIdx.x * 256 + threadIdx.x;
    if (idx >= NP*32) return;
    int n = idx >> 5, j = idx & 31;
    float inv_freq = expf(-(float)j * (9.210340371976184f / 32.f));
    float s, c;
    sincosf((float)n * inv_freq, &s, &c);
    float xscale = (2.f*(float)j + 25.6f) / 89.6f;
    float power = ((float)n - 1024.f) * (1.f/512.f);
    g_sin[idx] = s; g_cos[idx] = c; g_scale[idx] = expf(power * logf(xscale));
}

// ---------------- pre-split / convert ----------------
__global__ void convert_in(const float* __restrict__ q, const float* __restrict__ k,
                           const float* __restrict__ v) {
    int z = blockIdx.y;
    const float* src = (z == 0) ? q : (z == 1) ? k : v;
    int idx = (blockIdx.x * 256 + threadIdx.x) * 4;
    float4 x = *(const float4*)(src + idx);
    uint32_t h0,l0,h1,l1;
    split_pair_h(x.x, x.y, h0, l0);
    split_pair_h(x.z, x.w, h1, l1);
    *(uint2*)(&g_INh[z][idx]) = make_uint2(h0, h1);
    *(uint2*)(&g_INl[z][idx]) = make_uint2(l0, l1);
}
__global__ void convert_w(const float* __restrict__ w0, const float* __restrict__ w1,
                          const float* __restrict__ w2, const float* __restrict__ w3,
                          const float* __restrict__ w4) {
    int z = blockIdx.y;
    const float* src = (z == 0) ? w0 : (z == 1) ? w1 : (z == 2) ? w2 : (z == 3) ? w3 : w4;
    int idx = (blockIdx.x * 256 + threadIdx.x) * 4;
    float4 x = *(const float4*)(src + idx);
    *(uint2*)(&g_Wh[z][idx]) = make_uint2(pack_h(x.x, x.y), pack_h(x.z, x.w));
}

// ================= projection GEMM (fp16 x2, 4-stage K16 chunks, 2 CTA/SM) ========
// stage 18432B: AH@0 AL@6144 BH@12288; row stride 48B (16 fp16 + pad).
#define PSTG 18432
#define PROJ_SMEM (4*PSTG)

__device__ __forceinline__ void proj_load_stage(
    uint32_t sb, int stage,
    const __half* __restrict__ Ah, const __half* __restrict__ Al,
    const __half* __restrict__ Bh,
    int m0, int n0, int kc, int tid)
{
    uint32_t s0 = sb + stage * PSTG;
    int row = tid >> 1, seg = tid & 1;
    uint32_t so = (uint32_t)row*48 + seg*16;
    size_t ga = (size_t)(m0 + row)*EP + kc*16 + seg*8;
    size_t gb = (size_t)(n0 + row)*EP + kc*16 + seg*8;
    cp16(s0 +          so, Ah + ga);
    cp16(s0 + 6144 +   so, Al + ga);
    cp16(s0 + 12288 +  so, Bh + gb);
}

__device__ __forceinline__ void proj_body(
    const __half* __restrict__ Ah, const __half* __restrict__ Al,
    const __half* __restrict__ Bh,
    const float* __restrict__ bias, int epi,
    float* Cf, __half* Ch, __half* Cl, char* sm)
{
    const int tid = threadIdx.x, lane = tid & 31, wid = tid >> 5;
    const int wm = wid & 3, wn = wid >> 2;
    const int n0 = blockIdx.x * 128, m0 = blockIdx.y * 128;
    const uint32_t sb = smem_u32(sm);
    float acc[2][8][4] = {};

    proj_load_stage(sb, 0, Ah, Al, Bh, m0, n0, 0, tid); CP_COMMIT();
    proj_load_stage(sb, 1, Ah, Al, Bh, m0, n0, 1, tid); CP_COMMIT();
    proj_load_stage(sb, 2, Ah, Al, Bh, m0, n0, 2, tid); CP_COMMIT();

    for (int kc = 0; kc < 32; kc++) {
        CP_WAIT(2);
        __syncthreads();
        if (kc + 3 < 32)
            proj_load_stage(sb, (kc + 3) & 3, Ah, Al, Bh, m0, n0, kc + 3, tid);
        CP_COMMIT();

        const uint32_t base = sb + (kc & 3) * PSTG;
        uint32_t ah[2][4], al[2][4];
        #pragma unroll
        for (int mt = 0; mt < 2; mt++) {
            uint32_t off = (uint32_t)(wm*32 + mt*16 + (lane & 15))*48 + ((lane >> 4) & 1)*16;
            ldsm4(ah[mt], base + off);
            ldsm4(al[mt], base + 6144 + off);
        }
        #pragma unroll
        for (int jh = 0; jh < 2; jh++) {
            uint32_t bh[2][4];
            #pragma unroll
            for (int j = 0; j < 2; j++) {
                int jt = jh*2 + j;
                uint32_t off = (uint32_t)(wn*64 + jt*16 + (lane & 7) + ((lane & 16) ? 8 : 0))*48
                             + ((lane & 8) ? 16 : 0);
                ldsm4(bh[j], base + 12288 + off);
            }
            #pragma unroll
            for (int mt = 0; mt < 2; mt++)
                #pragma unroll
                for (int nn = 0; nn < 4; nn++) {
                    int nt = jh*4 + nn;
                    int j = nn >> 1, o = (nn & 1)*2;
                    mma_f16(acc[mt][nt], ah[mt], bh[j][o], bh[j][o+1]);
                    mma_f16(acc[mt][nt], al[mt], bh[j][o], bh[j][o+1]);
                }
        }
    }

    #pragma unroll
    for (int mt = 0; mt < 2; mt++) {
        #pragma unroll
        for (int rr = 0; rr < 2; rr++) {
            int row = m0 + wm*32 + mt*16 + (lane >> 2) + rr*8;
            int npos = row & (NP - 1);
            #pragma unroll
            for (int nt = 0; nt < 8; nt++) {
                int col = n0 + wn*64 + nt*8 + 2*(lane & 3);
                float x0 = acc[mt][nt][rr*2]     + bias[col];
                float x1 = acc[mt][nt][rr*2 + 1] + bias[col + 1];
                if (epi == 1) {
                    x0 = x0 / (1.f + expf(-x0));
                    x1 = x1 / (1.f + expf(-x1));
                } else if (epi == 2 || epi == 3) {
                    int j2 = (col & 63) >> 1;
                    float sn = g_sin[npos*32 + j2];
                    float cs = g_cos[npos*32 + j2];
                    float sc = g_scale[npos*32 + j2];
                    if (epi == 3) sc = 1.f / sc;
                    float s = sn * sc, c = cs * sc;
                    float y0 = x0 * c - x1 * s;
                    float y1 = x1 * c + x0 * s;
                    if (epi == 3) { y0 *= 0.125f; y1 *= 0.125f; }
                    x0 = y0; x1 = y1;
                }
                size_t off = (size_t)row*EP + col;
                if (Cf) {
                    *(float2*)(Cf + off) = make_float2(x0, x1);
                } else if (Cl) {
                    uint32_t hh, ll;
                    split_pair_h(x0, x1, hh, ll);
                    *(uint32_t*)(Ch + off) = hh;
                    *(uint32_t*)(Cl + off) = ll;
                } else {
                    *(uint32_t*)(Ch + off) = pack_h(x0, x1);
                }
            }
        }
    }
}

__global__ void __launch_bounds__(256, 2) qkvg_kernel(
    const float* __restrict__ bq, const float* __restrict__ bk,
    const float* __restrict__ bv, const float* __restrict__ bg)
{
    extern __shared__ char sm[];
    const int z = blockIdx.z;
    const __half* Ah = g_INh[(z == 3) ? 0 : z];
    const __half* Al = g_INl[(z == 3) ? 0 : z];
    const float* bias = (z == 0) ? bq : (z == 1) ? bk : (z == 2) ? bv : bg;
    __half* Ch = (z == 0) ? g_Qh : (z == 1) ? g_Kh : (z == 2) ? g_Vh : (__half*)0;
    __half* Cl = (z == 0) ? g_Ql : (__half*)0;
    float* Cf = (z == 3) ? g_G : (float*)0;
    const int epi = (z == 0) ? 2 : (z == 1) ? 3 : (z == 2) ? 0 : 1;
    proj_body(Ah, Al, g_Wh[z], bias, epi, Cf, Ch, Cl, sm);
}

__global__ void __launch_bounds__(256, 2) out_kernel(const float* __restrict__ bo,
                                                     float* __restrict__ out)
{
    extern __shared__ char sm[];
    proj_body(g_RGh, g_RGl, g_Wh[4], bo, 0, out, (__half*)0, (__half*)0, sm);
}

// ================= retention (fp16 x2, 64-row q-tiles, 128 thr, 2 CTA/SM) =========
// smem: QH@0 (64x144) QL@9216 | KV stage s @ 18432+s*18432 {KH+0, VH+9216}
#define RSM_QH 0u
#define RSM_QL 9216u
#define RSM_KV 18432u
#define KVSTG 18432u
#define RET_SMEM (18432u + 4u*18432u)   // 92160

__device__ __forceinline__ void kv_load_stage(uint32_t sb, int stage, int b, int h,
                                              int st, int tid)
{
    uint32_t s0 = sb + RSM_KV + (uint32_t)stage * KVSTG;
    #pragma unroll
    for (int i = 0; i < 4; i++) {
        int t = tid + i*128; int row = t >> 3, seg = t & 7;
        uint32_t so = (uint32_t)row*144 + seg*16;
        size_t ga = (size_t)(b*NP + st*64 + row)*EP + h*64 + seg*8;
        cp16(s0 +        so, g_Kh + ga);
        cp16(s0 + 9216 + so, g_Vh + ga);
    }
}

__global__ void __launch_bounds__(128, 2) retention_kernel()
{
    extern __shared__ char sm[];
    const int tid = threadIdx.x, lane = tid & 31, wid = tid >> 5;   // wid 0..3
    const int h = blockIdx.y, b = blockIdx.z;
    const uint32_t sb = smem_u32(sm);

    const float gamma = 1.f - expf(-(3.465735902799726f + 0.396084103177426f * (float)h));
    const float l2g = log2f(gamma);

    float colf[16];
    #pragma unroll
    for (int nt = 0; nt < 8; nt++) {
        int sl = nt*8 + 2*(lane & 3);
        colf[nt*2]   = exp2f(-l2g * (float)sl);
        colf[nt*2+1] = exp2f(-l2g * (float)(sl + 1));
    }
    const int nl0 = wid*16 + (lane >> 2);

    for (int phase = 0; phase < 2; phase++) {
        const int qt = phase ? (int)blockIdx.x : 31 - (int)blockIdx.x;
        const int n_st = qt + 1;

        // load Q tile (64 x 64, hi/lo fp16)
        #pragma unroll
        for (int i = 0; i < 4; i++) {
            int t = tid + i*128; int row = t >> 3, seg = t & 7;
            size_t ga = (size_t)(b*NP + qt*64 + row)*EP + h*64 + seg*8;
            *(uint4*)(sm + RSM_QH + row*144 + seg*16) = *(const uint4*)(g_Qh + ga);
            *(uint4*)(sm + RSM_QL + row*144 + seg*16) = *(const uint4*)(g_Ql + ga);
        }
        __syncthreads();   // prev-phase compute done + Q visible

        kv_load_stage(sb, 0, b, h, 0, tid); CP_COMMIT();
        if (n_st > 1) kv_load_stage(sb, 1, b, h, 1, tid);
        CP_COMMIT();
        if (n_st > 2) kv_load_stage(sb, 2, b, h, 2, tid);
        CP_COMMIT();

        uint32_t qh[4][4], ql[4][4];
        #pragma unroll
        for (int kk = 0; kk < 4; kk++) {
            uint32_t off = (uint32_t)(wid*16 + (lane & 15))*144 + kk*32 + ((lane >> 4) & 1)*16;
            ldsm4(qh[kk], sb + RSM_QH + off);
            ldsm4(ql[kk], sb + RSM_QL + off);
        }

        float ret[8][4] = {};

        for (int st = 0; st < n_st; st++) {
            CP_WAIT(2);
            __syncthreads();
            if (st + 3 < n_st) kv_load_stage(sb, (st + 3) & 3, b, h, st + 3, tid);
            CP_COMMIT();

            const uint32_t kvb = sb + RSM_KV + (uint32_t)(st & 3) * KVSTG;

            // gemm1: sim = Q K^T (k = 64)
            float simf[8][4] = {};
            #pragma unroll
            for (int kk = 0; kk < 4; kk++) {
                uint32_t bh[4][4];
                #pragma unroll
                for (int jt = 0; jt < 4; jt++) {
                    uint32_t off = (uint32_t)(jt*16 + (lane & 7) + ((lane & 16) ? 8 : 0))*144
                                 + kk*32 + ((lane & 8) ? 16 : 0);
                    ldsm4(bh[jt], kvb + off);
                }
                #pragma unroll
                for (int nt = 0; nt < 8; nt++) {
                    int jt = nt >> 1, o = (nt & 1)*2;
                    mma_f16(simf[nt], qh[kk], bh[jt][o], bh[jt][o+1]);
                    mma_f16(simf[nt], ql[kk], bh[jt][o], bh[jt][o+1]);
                }
            }

            // decay + mask + split -> fp16 A-fragments of gemm2 (registers only)
            const int db = qt*64 - st*64;
            const float brf0 = exp2f(l2g * (float)(db + nl0));
            const float brf1 = exp2f(l2g * (float)(db + nl0 + 8));
            uint32_t pa_h[8], pa_l[8], pb_h[8], pb_l[8];
            #pragma unroll
            for (int nt = 0; nt < 8; nt++) {
                int sl0 = nt*8 + 2*(lane & 3);
                float v00 = (db + nl0 - sl0     >= 0) ? simf[nt][0]*brf0*colf[nt*2]   : 0.f;
                float v01 = (db + nl0 - sl0 - 1 >= 0) ? simf[nt][1]*brf0*colf[nt*2+1] : 0.f;
                float v10 = (db + nl0 + 8 - sl0     >= 0) ? simf[nt][2]*brf1*colf[nt*2]   : 0.f;
                float v11 = (db + nl0 + 8 - sl0 - 1 >= 0) ? simf[nt][3]*brf1*colf[nt*2+1] : 0.f;
                split_pair_h(v00, v01, pa_h[nt], pa_l[nt]);
                split_pair_h(v10, v11, pb_h[nt], pb_l[nt]);
            }

            // gemm2: ret += sim @ V
            #pragma unroll
            for (int kk = 0; kk < 4; kk++) {
                uint32_t ah2[4] = { pa_h[2*kk], pb_h[2*kk], pa_h[2*kk+1], pb_h[2*kk+1] };
                uint32_t al2[4] = { pa_l[2*kk], pb_l[2*kk], pa_l[2*kk+1], pb_l[2*kk+1] };
                uint32_t bh[4][4];
                #pragma unroll
                for (int dt = 0; dt < 4; dt++) {
                    uint32_t off = (uint32_t)(kk*16 + (lane & 15))*144 + dt*32 + ((lane >> 4) & 1)*16;
                    ldsm4t(bh[dt], kvb + 9216 + off);
                }
                #pragma unroll
                for (int nt = 0; nt < 8; nt++) {
                    int dt = nt >> 1, o = (nt & 1)*2;
                    mma_f16(ret[nt], ah2, bh[dt][o], bh[dt][o+1]);
                    mma_f16(ret[nt], al2, bh[dt][o], bh[dt][o+1]);
                }
            }
        }

        // groupnorm + gate + write hi/lo fp16 planes
        #pragma unroll
        for (int rr = 0; rr < 2; rr++) {
            float s1 = 0.f, s2 = 0.f;
            #pragma unroll
            for (int nt = 0; nt < 8; nt++) {
                float a = ret[nt][rr*2], c = ret[nt][rr*2+1];
                s1 += a + c; s2 += a*a + c*c;
            }
            s1 += __shfl_xor_sync(0xffffffffu, s1, 1); s2 += __shfl_xor_sync(0xffffffffu, s2, 1);
            s1 += __shfl_xor_sync(0xffffffffu, s1, 2); s2 += __shfl_xor_sync(0xffffffffu, s2, 2);
            float mean = s1 * (1.f/64.f);
            float var  = s2 * (1.f/64.f) - mean*mean;
            float inv  = rsqrtf(var + 1e-6f);
            int row = qt*64 + nl0 + rr*8;
            size_t base = (size_t)(b*NP + row)*EP + h*64;
            #pragma unroll
            for (int nt = 0; nt < 8; nt++) {
                int col = nt*8 + 2*(lane & 3);
                float2 g2 = *(const float2*)(g_G + base + col);
                float x0 = (ret[nt][rr*2]   - mean)*inv * g2.x;
                float x1 = (ret[nt][rr*2+1] - mean)*inv * g2.y;
                uint32_t hh, ll;
                split_pair_h(x0, x1, hh, ll);
                *(uint32_t*)(g_RGh + base + col) = hh;
                *(uint32_t*)(g_RGl + base + col) = ll;
            }
        }
    }
}

// ---------------- launch ----------------
extern "C" void kernel_launch(void* const* d_in, const int* in_sizes, int n_in,
                              void* d_out, int out_size) {
    const float* query = (const float*)d_in[0];
    const float* key   = (const float*)d_in[1];
    const float* value = (const float*)d_in[2];
    const float* Wq = (const float*)d_in[3];
    const float* bq = (const float*)d_in[4];
    const float* Wk = (const float*)d_in[5];
    const float* bk = (const float*)d_in[6];
    const float* Wv = (const float*)d_in[7];
    const float* bv = (const float*)d_in[8];
    const float* Wg = (const float*)d_in[9];
    const float* bg = (const float*)d_in[10];
    const float* Wo = (const float*)d_in[11];
    const float* bo = (const float*)d_in[12];
    float* out = (float*)d_out;

    build_tables<<<(NP*32)/256, 256>>>();
    convert_in<<<dim3((MT*EP)/1024, 3), 256>>>(query, key, value);
    convert_w<<<dim3((EP*EP)/1024, 5), 256>>>(Wq, Wk, Wv, Wg, Wo);

    cudaFuncSetAttribute(qkvg_kernel, cudaFuncAttributeMaxDynamicSharedMemorySize, PROJ_SMEM);
    cudaFuncSetAttribute(out_kernel,  cudaFuncAttributeMaxDynamicSharedMemorySize, PROJ_SMEM);
    cudaFuncSetAttribute(retention_kernel, cudaFuncAttributeMaxDynamicSharedMemorySize, (int)RET_SMEM);

    qkvg_kernel<<<dim3(4, 32, 4), 256, PROJ_SMEM>>>(bq, bk, bv, bg);
    retention_kernel<<<dim3(16, 8, 2), 128, RET_SMEM>>>();
    out_kernel<<<dim3(4, 32, 1), 256, PROJ_SMEM>>>(bo, out);
}

// round 9
// speedup vs baseline: 3.9268x; 1.0459x over previous
#include <cuda_runtime.h>
#include <cuda_fp16.h>
#include <math.h>
#include <stdint.h>

#define NP 2048
#define EP 512
#define MT 4096

// ---------------- device scratch ----------------
__device__ __align__(16) float g_sin[NP*32];
__device__ __align__(16) float g_cos[NP*32];
__device__ __align__(16) float g_scale[NP*32];
__device__ __align__(16) __half g_INh[3][MT*EP];
__device__ __align__(16) __half g_INl[3][MT*EP];
__device__ __align__(16) __half g_Wh[5][EP*EP];
__device__ __align__(16) __half g_Qh[MT*EP], g_Ql[MT*EP];
__device__ __align__(16) __half g_Kh[MT*EP];
__device__ __align__(16) __half g_Vh[MT*EP];
__device__ __align__(16) __half g_RGh[MT*EP], g_RGl[MT*EP];
__device__ __align__(16) float g_G[MT*EP];

// ---------------- helpers ----------------
__device__ __forceinline__ uint32_t smem_u32(const void* p) {
    uint32_t a;
    asm("{ .reg .u64 t; cvta.to.shared.u64 t, %1; cvt.u32.u64 %0, t; }" : "=r"(a) : "l"(p));
    return a;
}
__device__ __forceinline__ void ldsm4(uint32_t* r, uint32_t a) {
    asm volatile("ldmatrix.sync.aligned.m8n8.x4.shared.b16 {%0,%1,%2,%3}, [%4];"
        : "=r"(r[0]), "=r"(r[1]), "=r"(r[2]), "=r"(r[3]) : "r"(a));
}
__device__ __forceinline__ void ldsm4t(uint32_t* r, uint32_t a) {
    asm volatile("ldmatrix.sync.aligned.m8n8.x4.trans.shared.b16 {%0,%1,%2,%3}, [%4];"
        : "=r"(r[0]), "=r"(r[1]), "=r"(r[2]), "=r"(r[3]) : "r"(a));
}
__device__ __forceinline__ void mma_f16(float* c, const uint32_t* a, uint32_t b0, uint32_t b1) {
    asm volatile("mma.sync.aligned.m16n8k16.row.col.f32.f16.f16.f32 "
        "{%0,%1,%2,%3}, {%4,%5,%6,%7}, {%8,%9}, {%0,%1,%2,%3};"
        : "+f"(c[0]), "+f"(c[1]), "+f"(c[2]), "+f"(c[3])
        : "r"(a[0]), "r"(a[1]), "r"(a[2]), "r"(a[3]), "r"(b0), "r"(b1));
}
__device__ __forceinline__ void split_pair_h(float v0, float v1, uint32_t& hi, uint32_t& lo) {
    __half h0 = __float2half_rn(v0);
    __half h1 = __float2half_rn(v1);
    __half l0 = __float2half_rn(v0 - __half2float(h0));
    __half l1 = __float2half_rn(v1 - __half2float(h1));
    __half2 H = __halves2half2(h0, h1);
    __half2 L = __halves2half2(l0, l1);
    hi = *reinterpret_cast<uint32_t*>(&H);
    lo = *reinterpret_cast<uint32_t*>(&L);
}
__device__ __forceinline__ uint32_t pack_h(float v0, float v1) {
    __half2 H = __floats2half2_rn(v0, v1);
    return *reinterpret_cast<uint32_t*>(&H);
}
__device__ __forceinline__ void cp16(uint32_t sdst, const void* gsrc) {
    asm volatile("cp.async.cg.shared.global [%0], [%1], 16;" :: "r"(sdst), "l"(gsrc) : "memory");
}
#define CP_COMMIT() asm volatile("cp.async.commit_group;" ::: "memory")
#define CP_WAIT(N)  asm volatile("cp.async.wait_group %0;" :: "n"(N) : "memory")

// ---------------- xpos tables ----------------
__global__ void build_tables() {
    int idx = blockIdx.x * 256 + threadIdx.x;
    if (idx >= NP*32) return;
    int n = idx >> 5, j = idx & 31;
    float inv_freq = expf(-(float)j * (9.210340371976184f / 32.f));
    float s, c;
    sincosf((float)n * inv_freq, &s, &c);
    float xscale = (2.f*(float)j + 25.6f) / 89.6f;
    float power = ((float)n - 1024.f) * (1.f/512.f);
    g_sin[idx] = s; g_cos[idx] = c; g_scale[idx] = expf(power * logf(xscale));
}

// ---------------- pre-split / convert ----------------
__global__ void convert_in(const float* __restrict__ q, const float* __restrict__ k,
                           const float* __restrict__ v) {
    int z = blockIdx.y;
    const float* src = (z == 0) ? q : (z == 1) ? k : v;
    int idx = (blockIdx.x * 256 + threadIdx.x) * 4;
    float4 x = *(const float4*)(src + idx);
    uint32_t h0,l0,h1,l1;
    split_pair_h(x.x, x.y, h0, l0);
    split_pair_h(x.z, x.w, h1, l1);
    *(uint2*)(&g_INh[z][idx]) = make_uint2(h0, h1);
    *(uint2*)(&g_INl[z][idx]) = make_uint2(l0, l1);
}
__global__ void convert_w(const float* __restrict__ w0, const float* __restrict__ w1,
                          const float* __restrict__ w2, const float* __restrict__ w3,
                          const float* __restrict__ w4) {
    int z = blockIdx.y;
    const float* src = (z == 0) ? w0 : (z == 1) ? w1 : (z == 2) ? w2 : (z == 3) ? w3 : w4;
    int idx = (blockIdx.x * 256 + threadIdx.x) * 4;
    float4 x = *(const float4*)(src + idx);
    *(uint2*)(&g_Wh[z][idx]) = make_uint2(pack_h(x.x, x.y), pack_h(x.z, x.w));
}

// ================= projection GEMM (fp16 x2, 3-stage K32 chunks, 2 CTA/SM) ========
// stage 30720B: AH@0 AL@10240 BH@20480; row stride 80B (32 fp16 + pad).
#define PSTG 30720
#define PROJ_SMEM (3*PSTG)

__device__ __forceinline__ void proj_load_stage(
    uint32_t sb, int stage,
    const __half* __restrict__ Ah, const __half* __restrict__ Al,
    const __half* __restrict__ Bh,
    int m0, int n0, int kc, int tid)
{
    uint32_t s0 = sb + stage * PSTG;
    // 3 planes x 128 rows x 64B = 1536 cp16 ops / 256 thr = 6 each
    #pragma unroll
    for (int i = 0; i < 2; i++) {
        int t = tid + i*256; int row = t >> 2, seg = t & 3;
        uint32_t so = (uint32_t)row*80 + seg*16;
        size_t ga = (size_t)(m0 + row)*EP + kc*32 + seg*8;
        size_t gb = (size_t)(n0 + row)*EP + kc*32 + seg*8;
        cp16(s0 +          so, Ah + ga);
        cp16(s0 + 10240 +  so, Al + ga);
        cp16(s0 + 20480 +  so, Bh + gb);
    }
}

__device__ __forceinline__ void proj_body(
    const __half* __restrict__ Ah, const __half* __restrict__ Al,
    const __half* __restrict__ Bh,
    const float* __restrict__ bias, int epi,
    float* Cf, __half* Ch, __half* Cl, char* sm)
{
    const int tid = threadIdx.x, lane = tid & 31, wid = tid >> 5;
    const int wm = wid & 3, wn = wid >> 2;
    const int n0 = blockIdx.x * 128, m0 = blockIdx.y * 128;
    const uint32_t sb = smem_u32(sm);
    float acc[2][8][4] = {};

    proj_load_stage(sb, 0, Ah, Al, Bh, m0, n0, 0, tid); CP_COMMIT();
    proj_load_stage(sb, 1, Ah, Al, Bh, m0, n0, 1, tid); CP_COMMIT();

    for (int kc = 0; kc < 16; kc++) {
        CP_WAIT(1);
        __syncthreads();
        if (kc + 2 < 16)
            proj_load_stage(sb, (kc + 2) % 3, Ah, Al, Bh, m0, n0, kc + 2, tid);
        CP_COMMIT();

        const uint32_t base = sb + (kc % 3) * PSTG;
        #pragma unroll
        for (int kk = 0; kk < 2; kk++) {
            uint32_t ah[2][4], al[2][4];
            #pragma unroll
            for (int mt = 0; mt < 2; mt++) {
                uint32_t off = (uint32_t)(wm*32 + mt*16 + (lane & 15))*80 + kk*32 + ((lane >> 4) & 1)*16;
                ldsm4(ah[mt], base + off);
                ldsm4(al[mt], base + 10240 + off);
            }
            #pragma unroll
            for (int jh = 0; jh < 2; jh++) {
                uint32_t bh[2][4];
                #pragma unroll
                for (int j = 0; j < 2; j++) {
                    int jt = jh*2 + j;
                    uint32_t off = (uint32_t)(wn*64 + jt*16 + (lane & 7) + ((lane & 16) ? 8 : 0))*80
                                 + kk*32 + ((lane & 8) ? 16 : 0);
                    ldsm4(bh[j], base + 20480 + off);
                }
                #pragma unroll
                for (int mt = 0; mt < 2; mt++)
                    #pragma unroll
                    for (int nn = 0; nn < 4; nn++) {
                        int nt = jh*4 + nn;
                        int j = nn >> 1, o = (nn & 1)*2;
                        mma_f16(acc[mt][nt], ah[mt], bh[j][o], bh[j][o+1]);
                        mma_f16(acc[mt][nt], al[mt], bh[j][o], bh[j][o+1]);
                    }
            }
        }
    }

    #pragma unroll
    for (int mt = 0; mt < 2; mt++) {
        #pragma unroll
        for (int rr = 0; rr < 2; rr++) {
            int row = m0 + wm*32 + mt*16 + (lane >> 2) + rr*8;
            int npos = row & (NP - 1);
            #pragma unroll
            for (int nt = 0; nt < 8; nt++) {
                int col = n0 + wn*64 + nt*8 + 2*(lane & 3);
                float x0 = acc[mt][nt][rr*2]     + bias[col];
                float x1 = acc[mt][nt][rr*2 + 1] + bias[col + 1];
                if (epi == 1) {
                    x0 = x0 / (1.f + expf(-x0));
                    x1 = x1 / (1.f + expf(-x1));
                } else if (epi == 2 || epi == 3) {
                    int j2 = (col & 63) >> 1;
                    float sn = g_sin[npos*32 + j2];
                    float cs = g_cos[npos*32 + j2];
                    float sc = g_scale[npos*32 + j2];
                    if (epi == 3) sc = 1.f / sc;
                    float s = sn * sc, c = cs * sc;
                    float y0 = x0 * c - x1 * s;
                    float y1 = x1 * c + x0 * s;
                    if (epi == 3) { y0 *= 0.125f; y1 *= 0.125f; }
                    x0 = y0; x1 = y1;
                }
                size_t off = (size_t)row*EP + col;
                if (Cf) {
                    *(float2*)(Cf + off) = make_float2(x0, x1);
                } else if (Cl) {
                    uint32_t hh, ll;
                    split_pair_h(x0, x1, hh, ll);
                    *(uint32_t*)(Ch + off) = hh;
                    *(uint32_t*)(Cl + off) = ll;
                } else {
                    *(uint32_t*)(Ch + off) = pack_h(x0, x1);
                }
            }
        }
    }
}

__global__ void __launch_bounds__(256, 2) qkvg_kernel(
    const float* __restrict__ bq, const float* __restrict__ bk,
    const float* __restrict__ bv, const float* __restrict__ bg)
{
    extern __shared__ char sm[];
    const int z = blockIdx.z;
    const __half* Ah = g_INh[(z == 3) ? 0 : z];
    const __half* Al = g_INl[(z == 3) ? 0 : z];
    const float* bias = (z == 0) ? bq : (z == 1) ? bk : (z == 2) ? bv : bg;
    __half* Ch = (z == 0) ? g_Qh : (z == 1) ? g_Kh : (z == 2) ? g_Vh : (__half*)0;
    __half* Cl = (z == 0) ? g_Ql : (__half*)0;
    float* Cf = (z == 3) ? g_G : (float*)0;
    const int epi = (z == 0) ? 2 : (z == 1) ? 3 : (z == 2) ? 0 : 1;
    proj_body(Ah, Al, g_Wh[z], bias, epi, Cf, Ch, Cl, sm);
}

__global__ void __launch_bounds__(256, 2) out_kernel(const float* __restrict__ bo,
                                                     float* __restrict__ out)
{
    extern __shared__ char sm[];
    proj_body(g_RGh, g_RGl, g_Wh[4], bo, 0, out, (__half*)0, (__half*)0, sm);
}

// ================= retention (fp16 x2, 64-row q-tiles, 128 thr, 3 CTA/SM) =========
// smem: QH@0 (64x144) QL@9216 | KV stage s @ 18432+s*18432 {KH+0, VH+9216}
#define RSM_QH 0u
#define RSM_QL 9216u
#define RSM_KV 18432u
#define KVSTG 18432u
#define RET_SMEM (18432u + 3u*18432u)   // 73728

__device__ __forceinline__ void kv_load_stage(uint32_t sb, int stage, int b, int h,
                                              int st, int tid)
{
    uint32_t s0 = sb + RSM_KV + (uint32_t)stage * KVSTG;
    #pragma unroll
    for (int i = 0; i < 4; i++) {
        int t = tid + i*128; int row = t >> 3, seg = t & 7;
        uint32_t so = (uint32_t)row*144 + seg*16;
        size_t ga = (size_t)(b*NP + st*64 + row)*EP + h*64 + seg*8;
        cp16(s0 +        so, g_Kh + ga);
        cp16(s0 + 9216 + so, g_Vh + ga);
    }
}

__global__ void __launch_bounds__(128, 3) retention_kernel()
{
    extern __shared__ char sm[];
    const int tid = threadIdx.x, lane = tid & 31, wid = tid >> 5;   // wid 0..3
    const int h = blockIdx.y, b = blockIdx.z;
    const uint32_t sb = smem_u32(sm);

    const float gamma = 1.f - expf(-(3.465735902799726f + 0.396084103177426f * (float)h));
    const float l2g = log2f(gamma);

    float colf[16];
    #pragma unroll
    for (int nt = 0; nt < 8; nt++) {
        int sl = nt*8 + 2*(lane & 3);
        colf[nt*2]   = exp2f(-l2g * (float)sl);
        colf[nt*2+1] = exp2f(-l2g * (float)(sl + 1));
    }
    const int nl0 = wid*16 + (lane >> 2);

    for (int phase = 0; phase < 2; phase++) {
        const int qt = phase ? (int)blockIdx.x : 31 - (int)blockIdx.x;
        const int n_st = qt + 1;

        // load Q tile (64 x 64, hi/lo fp16)
        #pragma unroll
        for (int i = 0; i < 4; i++) {
            int t = tid + i*128; int row = t >> 3, seg = t & 7;
            size_t ga = (size_t)(b*NP + qt*64 + row)*EP + h*64 + seg*8;
            *(uint4*)(sm + RSM_QH + row*144 + seg*16) = *(const uint4*)(g_Qh + ga);
            *(uint4*)(sm + RSM_QL + row*144 + seg*16) = *(const uint4*)(g_Ql + ga);
        }
        __syncthreads();   // prev-phase compute done + Q visible

        kv_load_stage(sb, 0, b, h, 0, tid); CP_COMMIT();
        if (n_st > 1) kv_load_stage(sb, 1, b, h, 1, tid);
        CP_COMMIT();

        uint32_t qh[4][4], ql[4][4];
        #pragma unroll
        for (int kk = 0; kk < 4; kk++) {
            uint32_t off = (uint32_t)(wid*16 + (lane & 15))*144 + kk*32 + ((lane >> 4) & 1)*16;
            ldsm4(qh[kk], sb + RSM_QH + off);
            ldsm4(ql[kk], sb + RSM_QL + off);
        }

        float ret[8][4] = {};

        for (int st = 0; st < n_st; st++) {
            CP_WAIT(1);
            __syncthreads();
            if (st + 2 < n_st) kv_load_stage(sb, (st + 2) % 3, b, h, st + 2, tid);
            CP_COMMIT();

            const uint32_t kvb = sb + RSM_KV + (uint32_t)(st % 3) * KVSTG;

            // gemm1: sim = Q K^T (k = 64)
            float simf[8][4] = {};
            #pragma unroll
            for (int kk = 0; kk < 4; kk++) {
                uint32_t bh[4][4];
                #pragma unroll
                for (int jt = 0; jt < 4; jt++) {
                    uint32_t off = (uint32_t)(jt*16 + (lane & 7) + ((lane & 16) ? 8 : 0))*144
                                 + kk*32 + ((lane & 8) ? 16 : 0);
                    ldsm4(bh[jt], kvb + off);
                }
                #pragma unroll
                for (int nt = 0; nt < 8; nt++) {
                    int jt = nt >> 1, o = (nt & 1)*2;
                    mma_f16(simf[nt], qh[kk], bh[jt][o], bh[jt][o+1]);
                    mma_f16(simf[nt], ql[kk], bh[jt][o], bh[jt][o+1]);
                }
            }

            // decay + mask + split -> fp16 A-fragments of gemm2 (registers only)
            const int db = qt*64 - st*64;
            const float brf0 = exp2f(l2g * (float)(db + nl0));
            const float brf1 = exp2f(l2g * (float)(db + nl0 + 8));
            uint32_t pa_h[8], pa_l[8], pb_h[8], pb_l[8];
            #pragma unroll
            for (int nt = 0; nt < 8; nt++) {
                int sl0 = nt*8 + 2*(lane & 3);
                float v00 = (db + nl0 - sl0     >= 0) ? simf[nt][0]*brf0*colf[nt*2]   : 0.f;
                float v01 = (db + nl0 - sl0 - 1 >= 0) ? simf[nt][1]*brf0*colf[nt*2+1] : 0.f;
                float v10 = (db + nl0 + 8 - sl0     >= 0) ? simf[nt][2]*brf1*colf[nt*2]   : 0.f;
                float v11 = (db + nl0 + 8 - sl0 - 1 >= 0) ? simf[nt][3]*brf1*colf[nt*2+1] : 0.f;
                split_pair_h(v00, v01, pa_h[nt], pa_l[nt]);
                split_pair_h(v10, v11, pb_h[nt], pb_l[nt]);
            }

            // gemm2: ret += sim @ V
            #pragma unroll
            for (int kk = 0; kk < 4; kk++) {
                uint32_t ah2[4] = { pa_h[2*kk], pb_h[2*kk], pa_h[2*kk+1], pb_h[2*kk+1] };
                uint32_t al2[4] = { pa_l[2*kk], pb_l[2*kk], pa_l[2*kk+1], pb_l[2*kk+1] };
                uint32_t bh[4][4];
                #pragma unroll
                for (int dt = 0; dt < 4; dt++) {
                    uint32_t off = (uint32_t)(kk*16 + (lane & 15))*144 + dt*32 + ((lane >> 4) & 1)*16;
                    ldsm4t(bh[dt], kvb + 9216 + off);
                }
                #pragma unroll
                for (int nt = 0; nt < 8; nt++) {
                    int dt = nt >> 1, o = (nt & 1)*2;
                    mma_f16(ret[nt], ah2, bh[dt][o], bh[dt][o+1]);
                    mma_f16(ret[nt], al2, bh[dt][o], bh[dt][o+1]);
                }
            }
        }

        // groupnorm + gate + write hi/lo fp16 planes
        #pragma unroll
        for (int rr = 0; rr < 2; rr++) {
            float s1 = 0.f, s2 = 0.f;
            #pragma unroll
            for (int nt = 0; nt < 8; nt++) {
                float a = ret[nt][rr*2], c = ret[nt][rr*2+1];
                s1 += a + c; s2 += a*a + c*c;
            }
            s1 += __shfl_xor_sync(0xffffffffu, s1, 1); s2 += __shfl_xor_sync(0xffffffffu, s2, 1);
            s1 += __shfl_xor_sync(0xffffffffu, s1, 2); s2 += __shfl_xor_sync(0xffffffffu, s2, 2);
            float mean = s1 * (1.f/64.f);
            float var  = s2 * (1.f/64.f) - mean*mean;
            float inv  = rsqrtf(var + 1e-6f);
            int row = qt*64 + nl0 + rr*8;
            size_t base = (size_t)(b*NP + row)*EP + h*64;
            #pragma unroll
            for (int nt = 0; nt < 8; nt++) {
                int col = nt*8 + 2*(lane & 3);
                float2 g2 = *(const float2*)(g_G + base + col);
                float x0 = (ret[nt][rr*2]   - mean)*inv * g2.x;
                float x1 = (ret[nt][rr*2+1] - mean)*inv * g2.y;
                uint32_t hh, ll;
                split_pair_h(x0, x1, hh, ll);
                *(uint32_t*)(g_RGh + base + col) = hh;
                *(uint32_t*)(g_RGl + base + col) = ll;
            }
        }
    }
}

// ---------------- launch ----------------
extern "C" void kernel_launch(void* const* d_in, const int* in_sizes, int n_in,
                              void* d_out, int out_size) {
    const float* query = (const float*)d_in[0];
    const float* key   = (const float*)d_in[1];
    const float* value = (const float*)d_in[2];
    const float* Wq = (const float*)d_in[3];
    const float* bq = (const float*)d_in[4];
    const float* Wk = (const float*)d_in[5];
    const float* bk = (const float*)d_in[6];
    const float* Wv = (const float*)d_in[7];
    const float* bv = (const float*)d_in[8];
    const float* Wg = (const float*)d_in[9];
    const float* bg = (const float*)d_in[10];
    const float* Wo = (const float*)d_in[11];
    const float* bo = (const float*)d_in[12];
    float* out = (float*)d_out;

    build_tables<<<(NP*32)/256, 256>>>();
    convert_in<<<dim3((MT*EP)/1024, 3), 256>>>(query, key, value);
    convert_w<<<dim3((EP*EP)/1024, 5), 256>>>(Wq, Wk, Wv, Wg, Wo);

    cudaFuncSetAttribute(qkvg_kernel, cudaFuncAttributeMaxDynamicSharedMemorySize, PROJ_SMEM);
    cudaFuncSetAttribute(out_kernel,  cudaFuncAttributeMaxDynamicSharedMemorySize, PROJ_SMEM);
    cudaFuncSetAttribute(retention_kernel, cudaFuncAttributeMaxDynamicSharedMemorySize, (int)RET_SMEM);

    qkvg_kernel<<<dim3(4, 32, 4), 256, PROJ_SMEM>>>(bq, bk, bv, bg);
    retention_kernel<<<dim3(16, 8, 2), 128, RET_SMEM>>>();
    out_kernel<<<dim3(4, 32, 1), 256, PROJ_SMEM>>>(bo, out);
}

// round 10
// speedup vs baseline: 4.3462x; 1.1068x over previous
#include <cuda_runtime.h>
#include <cuda_fp16.h>
#include <math.h>
#include <stdint.h>

#define NP 2048
#define EP 512
#define MT 4096

// ---------------- device scratch ----------------
__device__ __align__(16) float g_sin[NP*32];
__device__ __align__(16) float g_cos[NP*32];
__device__ __align__(16) float g_scale[NP*32];
__device__ __align__(16) __half g_INh[3][MT*EP];
__device__ __align__(16) __half g_INl[3][MT*EP];
__device__ __align__(16) __half g_Wh[5][EP*EP];
__device__ __align__(16) __half g_Qh[MT*EP], g_Ql[MT*EP];
__device__ __align__(16) __half g_Kh[MT*EP];
__device__ __align__(16) __half g_Vh[MT*EP];
__device__ __align__(16) __half g_RGh[MT*EP], g_RGl[MT*EP];
__device__ __align__(16) float g_G[MT*EP];

// ---------------- helpers ----------------
__device__ __forceinline__ uint32_t smem_u32(const void* p) {
    uint32_t a;
    asm("{ .reg .u64 t; cvta.to.shared.u64 t, %1; cvt.u32.u64 %0, t; }" : "=r"(a) : "l"(p));
    return a;
}
__device__ __forceinline__ void ldsm4(uint32_t* r, uint32_t a) {
    asm volatile("ldmatrix.sync.aligned.m8n8.x4.shared.b16 {%0,%1,%2,%3}, [%4];"
        : "=r"(r[0]), "=r"(r[1]), "=r"(r[2]), "=r"(r[3]) : "r"(a));
}
__device__ __forceinline__ void ldsm4t(uint32_t* r, uint32_t a) {
    asm volatile("ldmatrix.sync.aligned.m8n8.x4.trans.shared.b16 {%0,%1,%2,%3}, [%4];"
        : "=r"(r[0]), "=r"(r[1]), "=r"(r[2]), "=r"(r[3]) : "r"(a));
}
__device__ __forceinline__ void mma_f16(float* c, const uint32_t* a, uint32_t b0, uint32_t b1) {
    asm volatile("mma.sync.aligned.m16n8k16.row.col.f32.f16.f16.f32 "
        "{%0,%1,%2,%3}, {%4,%5,%6,%7}, {%8,%9}, {%0,%1,%2,%3};"
        : "+f"(c[0]), "+f"(c[1]), "+f"(c[2]), "+f"(c[3])
        : "r"(a[0]), "r"(a[1]), "r"(a[2]), "r"(a[3]), "r"(b0), "r"(b1));
}
__device__ __forceinline__ void split_pair_h(float v0, float v1, uint32_t& hi, uint32_t& lo) {
    __half h0 = __float2half_rn(v0);
    __half h1 = __float2half_rn(v1);
    __half l0 = __float2half_rn(v0 - __half2float(h0));
    __half l1 = __float2half_rn(v1 - __half2float(h1));
    __half2 H = __halves2half2(h0, h1);
    __half2 L = __halves2half2(l0, l1);
    hi = *reinterpret_cast<uint32_t*>(&H);
    lo = *reinterpret_cast<uint32_t*>(&L);
}
__device__ __forceinline__ uint32_t pack_h(float v0, float v1) {
    __half2 H = __floats2half2_rn(v0, v1);
    return *reinterpret_cast<uint32_t*>(&H);
}
__device__ __forceinline__ void cp16(uint32_t sdst, const void* gsrc) {
    asm volatile("cp.async.cg.shared.global [%0], [%1], 16;" :: "r"(sdst), "l"(gsrc) : "memory");
}
#define CP_COMMIT() asm volatile("cp.async.commit_group;" ::: "memory")
#define CP_WAIT(N)  asm volatile("cp.async.wait_group %0;" :: "n"(N) : "memory")

// ---------------- xpos tables ----------------
__global__ void build_tables() {
    int idx = blockIdx.x * 256 + threadIdx.x;
    if (idx >= NP*32) return;
    int n = idx >> 5, j = idx & 31;
    float inv_freq = expf(-(float)j * (9.210340371976184f / 32.f));
    float s, c;
    sincosf((float)n * inv_freq, &s, &c);
    float xscale = (2.f*(float)j + 25.6f) / 89.6f;
    float power = ((float)n - 1024.f) * (1.f/512.f);
    g_sin[idx] = s; g_cos[idx] = c; g_scale[idx] = expf(power * logf(xscale));
}

// ---------------- pre-split / convert ----------------
__global__ void convert_in(const float* __restrict__ q, const float* __restrict__ k,
                           const float* __restrict__ v) {
    int z = blockIdx.y;
    const float* src = (z == 0) ? q : (z == 1) ? k : v;
    int idx = (blockIdx.x * 256 + threadIdx.x) * 4;
    float4 x = *(const float4*)(src + idx);
    uint32_t h0,l0,h1,l1;
    split_pair_h(x.x, x.y, h0, l0);
    split_pair_h(x.z, x.w, h1, l1);
    *(uint2*)(&g_INh[z][idx]) = make_uint2(h0, h1);
    *(uint2*)(&g_INl[z][idx]) = make_uint2(l0, l1);
}
__global__ void convert_w(const float* __restrict__ w0, const float* __restrict__ w1,
                          const float* __restrict__ w2, const float* __restrict__ w3,
                          const float* __restrict__ w4) {
    int z = blockIdx.y;
    const float* src = (z == 0) ? w0 : (z == 1) ? w1 : (z == 2) ? w2 : (z == 3) ? w3 : w4;
    int idx = (blockIdx.x * 256 + threadIdx.x) * 4;
    float4 x = *(const float4*)(src + idx);
    *(uint2*)(&g_Wh[z][idx]) = make_uint2(pack_h(x.x, x.y), pack_h(x.z, x.w));
}

// ===== projection GEMM (fp16 x2, M64xN128 tile, warp 32x32, 3-stage K32, 3 CTA/SM) =====
// stage 20480B: AH@0 (64x80B) AL@5120 BH@10240 (128x80B)
#define PSTG 20480
#define PROJ_SMEM (3*PSTG)

__device__ __forceinline__ void proj_load_stage(
    uint32_t sb, int stage,
    const __half* __restrict__ Ah, const __half* __restrict__ Al,
    const __half* __restrict__ Bh,
    int m0, int n0, int kc, int tid)
{
    uint32_t s0 = sb + stage * PSTG;
    {   // A hi + lo: 64 rows x 4 segs, 256 threads -> 1 op each per plane
        int row = tid >> 2, seg = tid & 3;
        uint32_t so = (uint32_t)row*80 + seg*16;
        size_t ga = (size_t)(m0 + row)*EP + kc*32 + seg*8;
        cp16(s0 +         so, Ah + ga);
        cp16(s0 + 5120 +  so, Al + ga);
    }
    #pragma unroll
    for (int i = 0; i < 2; i++) {   // B hi: 128 rows x 4 segs = 512 ops
        int t = tid + i*256; int row = t >> 2, seg = t & 3;
        uint32_t so = (uint32_t)row*80 + seg*16;
        size_t gb = (size_t)(n0 + row)*EP + kc*32 + seg*8;
        cp16(s0 + 10240 + so, Bh + gb);
    }
}

__device__ __forceinline__ void proj_body(
    const __half* __restrict__ Ah, const __half* __restrict__ Al,
    const __half* __restrict__ Bh,
    const float* __restrict__ bias, int epi,
    float* Cf, __half* Ch, __half* Cl, char* sm)
{
    const int tid = threadIdx.x, lane = tid & 31, wid = tid >> 5;
    const int wm = wid & 1, wn = wid >> 1;          // 2 m-warps x 4 n-warps
    const int n0 = blockIdx.x * 128, m0 = blockIdx.y * 64;
    const uint32_t sb = smem_u32(sm);
    float acc[2][4][4] = {};

    proj_load_stage(sb, 0, Ah, Al, Bh, m0, n0, 0, tid); CP_COMMIT();
    proj_load_stage(sb, 1, Ah, Al, Bh, m0, n0, 1, tid); CP_COMMIT();

    for (int kc = 0; kc < 16; kc++) {
        CP_WAIT(1);
        __syncthreads();
        if (kc + 2 < 16)
            proj_load_stage(sb, (kc + 2) % 3, Ah, Al, Bh, m0, n0, kc + 2, tid);
        CP_COMMIT();

        const uint32_t base = sb + (kc % 3) * PSTG;
        #pragma unroll
        for (int kk = 0; kk < 2; kk++) {
            uint32_t ah[2][4], al[2][4];
            #pragma unroll
            for (int mt = 0; mt < 2; mt++) {
                uint32_t off = (uint32_t)(wm*32 + mt*16 + (lane & 15))*80 + kk*32 + ((lane >> 4) & 1)*16;
                ldsm4(ah[mt], base + off);
                ldsm4(al[mt], base + 5120 + off);
            }
            uint32_t bh[2][4];
            #pragma unroll
            for (int jt = 0; jt < 2; jt++) {
                uint32_t off = (uint32_t)(wn*32 + jt*16 + (lane & 7) + ((lane & 16) ? 8 : 0))*80
                             + kk*32 + ((lane & 8) ? 16 : 0);
                ldsm4(bh[jt], base + 10240 + off);
            }
            #pragma unroll
            for (int mt = 0; mt < 2; mt++)
                #pragma unroll
                for (int nt = 0; nt < 4; nt++) {
                    int jt = nt >> 1, o = (nt & 1)*2;
                    mma_f16(acc[mt][nt], ah[mt], bh[jt][o], bh[jt][o+1]);
                    mma_f16(acc[mt][nt], al[mt], bh[jt][o], bh[jt][o+1]);
                }
        }
    }

    #pragma unroll
    for (int mt = 0; mt < 2; mt++) {
        #pragma unroll
        for (int rr = 0; rr < 2; rr++) {
            int row = m0 + wm*32 + mt*16 + (lane >> 2) + rr*8;
            int npos = row & (NP - 1);
            #pragma unroll
            for (int nt = 0; nt < 4; nt++) {
                int col = n0 + wn*32 + nt*8 + 2*(lane & 3);
                float x0 = acc[mt][nt][rr*2]     + bias[col];
                float x1 = acc[mt][nt][rr*2 + 1] + bias[col + 1];
                if (epi == 1) {
                    x0 = x0 / (1.f + expf(-x0));
                    x1 = x1 / (1.f + expf(-x1));
                } else if (epi == 2 || epi == 3) {
                    int j2 = (col & 63) >> 1;
                    float sn = g_sin[npos*32 + j2];
                    float cs = g_cos[npos*32 + j2];
                    float sc = g_scale[npos*32 + j2];
                    if (epi == 3) sc = 1.f / sc;
                    float s = sn * sc, c = cs * sc;
                    float y0 = x0 * c - x1 * s;
                    float y1 = x1 * c + x0 * s;
                    if (epi == 3) { y0 *= 0.125f; y1 *= 0.125f; }
                    x0 = y0; x1 = y1;
                }
                size_t off = (size_t)row*EP + col;
                if (Cf) {
                    *(float2*)(Cf + off) = make_float2(x0, x1);
                } else if (Cl) {
                    uint32_t hh, ll;
                    split_pair_h(x0, x1, hh, ll);
                    *(uint32_t*)(Ch + off) = hh;
                    *(uint32_t*)(Cl + off) = ll;
                } else {
                    *(uint32_t*)(Ch + off) = pack_h(x0, x1);
                }
            }
        }
    }
}

__global__ void __launch_bounds__(256, 3) qkvg_kernel(
    const float* __restrict__ bq, const float* __restrict__ bk,
    const float* __restrict__ bv, const float* __restrict__ bg)
{
    extern __shared__ char sm[];
    const int z = blockIdx.z;
    const __half* Ah = g_INh[(z == 3) ? 0 : z];
    const __half* Al = g_INl[(z == 3) ? 0 : z];
    const float* bias = (z == 0) ? bq : (z == 1) ? bk : (z == 2) ? bv : bg;
    __half* Ch = (z == 0) ? g_Qh : (z == 1) ? g_Kh : (z == 2) ? g_Vh : (__half*)0;
    __half* Cl = (z == 0) ? g_Ql : (__half*)0;
    float* Cf = (z == 3) ? g_G : (float*)0;
    const int epi = (z == 0) ? 2 : (z == 1) ? 3 : (z == 2) ? 0 : 1;
    proj_body(Ah, Al, g_Wh[z], bias, epi, Cf, Ch, Cl, sm);
}

__global__ void __launch_bounds__(256, 3) out_kernel(const float* __restrict__ bo,
                                                     float* __restrict__ out)
{
    extern __shared__ char sm[];
    proj_body(g_RGh, g_RGl, g_Wh[4], bo, 0, out, (__half*)0, (__half*)0, sm);
}

// ================= retention (fp16 x2, 64-row q-tiles, 128 thr, 3 CTA/SM) =========
// smem: QH@0 (64x144) QL@9216 | KV stage s @ 18432+s*18432 {KH+0, VH+9216}
#define RSM_QH 0u
#define RSM_QL 9216u
#define RSM_KV 18432u
#define KVSTG 18432u
#define RET_SMEM (18432u + 3u*18432u)   // 73728

__device__ __forceinline__ void kv_load_stage(uint32_t sb, int stage, int b, int h,
                                              int st, int tid)
{
    uint32_t s0 = sb + RSM_KV + (uint32_t)stage * KVSTG;
    #pragma unroll
    for (int i = 0; i < 4; i++) {
        int t = tid + i*128; int row = t >> 3, seg = t & 7;
        uint32_t so = (uint32_t)row*144 + seg*16;
        size_t ga = (size_t)(b*NP + st*64 + row)*EP + h*64 + seg*8;
        cp16(s0 +        so, g_Kh + ga);
        cp16(s0 + 9216 + so, g_Vh + ga);
    }
}

__global__ void __launch_bounds__(128, 3) retention_kernel()
{
    extern __shared__ char sm[];
    const int tid = threadIdx.x, lane = tid & 31, wid = tid >> 5;   // wid 0..3
    const int h = blockIdx.y, b = blockIdx.z;
    const uint32_t sb = smem_u32(sm);

    const float gamma = 1.f - expf(-(3.465735902799726f + 0.396084103177426f * (float)h));
    const float l2g = log2f(gamma);

    float colf[16];
    #pragma unroll
    for (int nt = 0; nt < 8; nt++) {
        int sl = nt*8 + 2*(lane & 3);
        colf[nt*2]   = exp2f(-l2g * (float)sl);
        colf[nt*2+1] = exp2f(-l2g * (float)(sl + 1));
    }
    const int nl0 = wid*16 + (lane >> 2);

    for (int phase = 0; phase < 2; phase++) {
        const int qt = phase ? (int)blockIdx.x : 31 - (int)blockIdx.x;
        const int n_st = qt + 1;

        // load Q tile (64 x 64, hi/lo fp16)
        #pragma unroll
        for (int i = 0; i < 4; i++) {
            int t = tid + i*128; int row = t >> 3, seg = t & 7;
            size_t ga = (size_t)(b*NP + qt*64 + row)*EP + h*64 + seg*8;
            *(uint4*)(sm + RSM_QH + row*144 + seg*16) = *(const uint4*)(g_Qh + ga);
            *(uint4*)(sm + RSM_QL + row*144 + seg*16) = *(const uint4*)(g_Ql + ga);
        }
        __syncthreads();   // prev-phase compute done + Q visible

        kv_load_stage(sb, 0, b, h, 0, tid); CP_COMMIT();
        if (n_st > 1) kv_load_stage(sb, 1, b, h, 1, tid);
        CP_COMMIT();

        uint32_t qh[4][4], ql[4][4];
        #pragma unroll
        for (int kk = 0; kk < 4; kk++) {
            uint32_t off = (uint32_t)(wid*16 + (lane & 15))*144 + kk*32 + ((lane >> 4) & 1)*16;
            ldsm4(qh[kk], sb + RSM_QH + off);
            ldsm4(ql[kk], sb + RSM_QL + off);
        }

        float ret[8][4] = {};

        for (int st = 0; st < n_st; st++) {
            CP_WAIT(1);
            __syncthreads();
            if (st + 2 < n_st) kv_load_stage(sb, (st + 2) % 3, b, h, st + 2, tid);
            CP_COMMIT();

            const uint32_t kvb = sb + RSM_KV + (uint32_t)(st % 3) * KVSTG;

            // gemm1: sim = Q K^T (k = 64)
            float simf[8][4] = {};
            #pragma unroll
            for (int kk = 0; kk < 4; kk++) {
                uint32_t bh[4][4];
                #pragma unroll
                for (int jt = 0; jt < 4; jt++) {
                    uint32_t off = (uint32_t)(jt*16 + (lane & 7) + ((lane & 16) ? 8 : 0))*144
                                 + kk*32 + ((lane & 8) ? 16 : 0);
                    ldsm4(bh[jt], kvb + off);
                }
                #pragma unroll
                for (int nt = 0; nt < 8; nt++) {
                    int jt = nt >> 1, o = (nt & 1)*2;
                    mma_f16(simf[nt], qh[kk], bh[jt][o], bh[jt][o+1]);
                    mma_f16(simf[nt], ql[kk], bh[jt][o], bh[jt][o+1]);
                }
            }

            // decay + mask + split -> fp16 A-fragments of gemm2 (registers only)
            const int db = qt*64 - st*64;
            const float brf0 = exp2f(l2g * (float)(db + nl0));
            const float brf1 = exp2f(l2g * (float)(db + nl0 + 8));
            uint32_t pa_h[8], pa_l[8], pb_h[8], pb_l[8];
            #pragma unroll
            for (int nt = 0; nt < 8; nt++) {
                int sl0 = nt*8 + 2*(lane & 3);
                float v00 = (db + nl0 - sl0     >= 0) ? simf[nt][0]*brf0*colf[nt*2]   : 0.f;
                float v01 = (db + nl0 - sl0 - 1 >= 0) ? simf[nt][1]*brf0*colf[nt*2+1] : 0.f;
                float v10 = (db + nl0 + 8 - sl0     >= 0) ? simf[nt][2]*brf1*colf[nt*2]   : 0.f;
                float v11 = (db + nl0 + 8 - sl0 - 1 >= 0) ? simf[nt][3]*brf1*colf[nt*2+1] : 0.f;
                split_pair_h(v00, v01, pa_h[nt], pa_l[nt]);
                split_pair_h(v10, v11, pb_h[nt], pb_l[nt]);
            }

            // gemm2: ret += sim @ V
            #pragma unroll
            for (int kk = 0; kk < 4; kk++) {
                uint32_t ah2[4] = { pa_h[2*kk], pb_h[2*kk], pa_h[2*kk+1], pb_h[2*kk+1] };
                uint32_t al2[4] = { pa_l[2*kk], pb_l[2*kk], pa_l[2*kk+1], pb_l[2*kk+1] };
                uint32_t bh[4][4];
                #pragma unroll
                for (int dt = 0; dt < 4; dt++) {
                    uint32_t off = (uint32_t)(kk*16 + (lane & 15))*144 + dt*32 + ((lane >> 4) & 1)*16;
                    ldsm4t(bh[dt], kvb + 9216 + off);
                }
                #pragma unroll
                for (int nt = 0; nt < 8; nt++) {
                    int dt = nt >> 1, o = (nt & 1)*2;
                    mma_f16(ret[nt], ah2, bh[dt][o], bh[dt][o+1]);
                    mma_f16(ret[nt], al2, bh[dt][o], bh[dt][o+1]);
                }
            }
        }

        // groupnorm + gate + write hi/lo fp16 planes
        #pragma unroll
        for (int rr = 0; rr < 2; rr++) {
            float s1 = 0.f, s2 = 0.f;
            #pragma unroll
            for (int nt = 0; nt < 8; nt++) {
                float a = ret[nt][rr*2], c = ret[nt][rr*2+1];
                s1 += a + c; s2 += a*a + c*c;
            }
            s1 += __shfl_xor_sync(0xffffffffu, s1, 1); s2 += __shfl_xor_sync(0xffffffffu, s2, 1);
            s1 += __shfl_xor_sync(0xffffffffu, s1, 2); s2 += __shfl_xor_sync(0xffffffffu, s2, 2);
            float mean = s1 * (1.f/64.f);
            float var  = s2 * (1.f/64.f) - mean*mean;
            float inv  = rsqrtf(var + 1e-6f);
            int row = qt*64 + nl0 + rr*8;
            size_t base = (size_t)(b*NP + row)*EP + h*64;
            #pragma unroll
            for (int nt = 0; nt < 8; nt++) {
                int col = nt*8 + 2*(lane & 3);
                float2 g2 = *(const float2*)(g_G + base + col);
                float x0 = (ret[nt][rr*2]   - mean)*inv * g2.x;
                float x1 = (ret[nt][rr*2+1] - mean)*inv * g2.y;
                uint32_t hh, ll;
                split_pair_h(x0, x1, hh, ll);
                *(uint32_t*)(g_RGh + base + col) = hh;
                *(uint32_t*)(g_RGl + base + col) = ll;
            }
        }
    }
}

// ---------------- launch ----------------
extern "C" void kernel_launch(void* const* d_in, const int* in_sizes, int n_in,
                              void* d_out, int out_size) {
    const float* query = (const float*)d_in[0];
    const float* key   = (const float*)d_in[1];
    const float* value = (const float*)d_in[2];
    const float* Wq = (const float*)d_in[3];
    const float* bq = (const float*)d_in[4];
    const float* Wk = (const float*)d_in[5];
    const float* bk = (const float*)d_in[6];
    const float* Wv = (const float*)d_in[7];
    const float* bv = (const float*)d_in[8];
    const float* Wg = (const float*)d_in[9];
    const float* bg = (const float*)d_in[10];
    const float* Wo = (const float*)d_in[11];
    const float* bo = (const float*)d_in[12];
    float* out = (float*)d_out;

    build_tables<<<(NP*32)/256, 256>>>();
    convert_in<<<dim3((MT*EP)/1024, 3), 256>>>(query, key, value);
    convert_w<<<dim3((EP*EP)/1024, 5), 256>>>(Wq, Wk, Wv, Wg, Wo);

    cudaFuncSetAttribute(qkvg_kernel, cudaFuncAttributeMaxDynamicSharedMemorySize, PROJ_SMEM);
    cudaFuncSetAttribute(out_kernel,  cudaFuncAttributeMaxDynamicSharedMemorySize, PROJ_SMEM);
    cudaFuncSetAttribute(retention_kernel, cudaFuncAttributeMaxDynamicSharedMemorySize, (int)RET_SMEM);

    qkvg_kernel<<<dim3(4, 64, 4), 256, PROJ_SMEM>>>(bq, bk, bv, bg);
    retention_kernel<<<dim3(16, 8, 2), 128, RET_SMEM>>>();
    out_kernel<<<dim3(4, 64, 1), 256, PROJ_SMEM>>>(bo, out);
}